// round 12
// baseline (speedup 1.0000x reference)
#include <cuda_runtime.h>
#include <cuda_fp16.h>
#include <cstdint>

#define BB 8
#define LL 4096
#define HH 512
#define NN 16
#define NLAYERS 4

typedef unsigned long long u64;

__device__ __forceinline__ u64 pk2(float lo, float hi) {
    u64 r; asm("mov.b64 %0,{%1,%2};" : "=l"(r) : "f"(lo), "f"(hi)); return r;
}
__device__ __forceinline__ void upk2(u64 v, float& lo, float& hi) {
    asm("mov.b64 {%0,%1},%2;" : "=f"(lo), "=f"(hi) : "l"(v));
}
__device__ __forceinline__ u64 f2fma(u64 a, u64 b, u64 c) {
    u64 d; asm("fma.rn.f32x2 %0,%1,%2,%3;" : "=l"(d) : "l"(a), "l"(b), "l"(c)); return d;
}
__device__ __forceinline__ uint32_t smem_u32(const void* p) {
    uint32_t a;
    asm("{ .reg .u64 t; cvta.to.shared.u64 t, %1; cvt.u32.u64 %0, t; }" : "=r"(a) : "l"(p));
    return a;
}
__device__ __forceinline__ void cpa16(uint32_t dst, const void* src) {
    asm volatile("cp.async.cg.shared.global [%0],[%1],16;" :: "r"(dst), "l"(src));
}

// ---------------- scratch ----------------------------------------------------
__device__ float g_h [BB*LL*HH];
__device__ float g_ut[(size_t)BB*HH*LL];
__device__ float g_w [NLAYERS*HH*NN*2];
__device__ float g_ct[NLAYERS*2*HH*NN*2];
__device__ __half g_yh[(size_t)BB*HH*LL];   // (B,H,L) fp16 hi
__device__ __half g_yl[(size_t)BB*HH*LL];   // (B,H,L) fp16 lo
__device__ __half g_wh[NLAYERS*2*HH*HH];

// ---------------- prep: encoder + W->fp16 + SSM params, one kernel -----------
__global__ void k_prep(const float* __restrict__ x, const float* __restrict__ enc_w,
                       const float* __restrict__ enc_b, const float* __restrict__ out_w,
                       const float* __restrict__ log_dt, const float* __restrict__ A_re,
                       const float* __restrict__ A_im, const float* __restrict__ C_re,
                       const float* __restrict__ C_im) {
    int idx = blockIdx.x * blockDim.x + threadIdx.x;   // grid covers B*L*H
    int hh = idx % HH;
    int l  = (idx / HH) % LL;
    int b  = idx / (LL*HH);
    float grid = (float)l * (1.0f/(LL-1));
    g_h[idx] = enc_w[hh*2+0]*x[b*LL + l] + enc_w[hh*2+1]*grid + enc_b[hh];
    if (idx < NLAYERS*2*HH*HH) g_wh[idx] = __float2half(out_w[idx]);

    if (idx < NLAYERS*HH*NN) {
        int n     = idx % NN;
        int h     = (idx / NN) % HH;
        int layer = idx / (HH*NN);
        float dt  = expf(log_dt[layer*HH + h]);
        float are = A_re[idx];
        float aim = A_im[idx];
        float e   = expf(are*dt);
        float wre = e * cosf(aim*dt);
        float wim = e * sinf(aim*dt);
        g_w[idx*2+0] = wre;
        g_w[idx*2+1] = wim;
        float inv = 1.0f / (are*are + aim*aim);
        float nre = wre - 1.0f, nim = wim;
        float fre = (nre*are + nim*aim) * inv;
        float fim = (nim*are - nre*aim) * inv;
        #pragma unroll
        for (int c = 0; c < 2; c++) {
            int cidx = ((layer*2 + c)*HH + h)*NN + n;
            float cre = C_re[cidx], cim = C_im[cidx];
            g_ct[cidx*2+0] = 2.0f*(cre*fre - cim*fim);
            g_ct[cidx*2+1] = 2.0f*(cre*fim + cim*fre);
        }
    }
}

// ---------------- LayerNorm + transpose to (B,H,L) ---------------------------
__global__ void __launch_bounds__(256) k_ln_t(const float* __restrict__ ln_w,
                                              const float* __restrict__ ln_b, int layer) {
    __shared__ float s_mean[32], s_rstd[32];
    __shared__ float tile[64][33];
    int b  = blockIdx.y;
    int l0 = blockIdx.x * 32;
    int tid = threadIdx.x, warp = tid >> 5, lane = tid & 31;
    const float* lw = ln_w + layer*HH;
    const float* lb = ln_b + layer*HH;

    for (int r = warp; r < 32; r += 8) {
        const float4* row = (const float4*)(g_h + ((size_t)b*LL + l0 + r)*HH);
        float sum = 0.f, sq = 0.f;
        #pragma unroll
        for (int j = 0; j < 4; j++) {
            float4 v = row[lane + 32*j];
            sum += v.x + v.y + v.z + v.w;
            sq  += v.x*v.x + v.y*v.y + v.z*v.z + v.w*v.w;
        }
        #pragma unroll
        for (int o = 16; o > 0; o >>= 1) {
            sum += __shfl_xor_sync(0xffffffffu, sum, o);
            sq  += __shfl_xor_sync(0xffffffffu, sq , o);
        }
        if (lane == 0) {
            float mu = sum * (1.0f/HH);
            s_mean[r] = mu;
            s_rstd[r] = rsqrtf(sq * (1.0f/HH) - mu*mu + 1e-5f);
        }
    }
    __syncthreads();

    for (int h0 = 0; h0 < HH; h0 += 64) {
        #pragma unroll
        for (int p = 0; p < 8; p++) {
            int r = p*4 + (tid >> 6);
            int c = tid & 63;
            float v = g_h[((size_t)b*LL + l0 + r)*HH + h0 + c];
            tile[c][r] = (v - s_mean[r]) * s_rstd[r] * lw[h0 + c] + lb[h0 + c];
        }
        __syncthreads();
        #pragma unroll
        for (int p = 0; p < 8; p++) {
            int hh = p*8 + (tid >> 5);
            int lc = tid & 31;
            g_ut[((size_t)b*HH + h0 + hh)*LL + l0 + lc] = tile[hh][lc];
        }
        __syncthreads();
    }
}

// ---------------- bidirectional SSM scan: 8 modes/thread ---------------------
// 256 threads = 64 chunks(64 steps) x 2 dirs x 2 n-threads (8 n each, 4 pairs).
__global__ void __launch_bounds__(256, 3) k_scan(const float* __restrict__ Din, int layer) {
    __shared__ float su[4161];                  // skewed: idx = t + (t>>6)
    __shared__ __align__(8) char uni[16648];    // union: chunk-state (16KB) / sy
    u64*   st = (u64*)uni;
    float* sy = (float*)uni;

    int bh = blockIdx.x;
    int h  = bh & 511;
    int tid = threadIdx.x;
    const float* urow = g_ut + (size_t)bh * LL;

    for (int t = tid; t < 4096; t += 256) su[t + (t >> 6)] = urow[t];
    if (tid == 0) su[4160] = 0.0f;              // u[4096] = 0 pad
    __syncthreads();

    int n2    = tid & 1;                        // owns pairs P = 4*n2 + j
    int dir   = (tid >> 1) & 1;
    int chunk = tid >> 2;                       // 0..63
    int t0    = chunk << 6;

    const float* wb = g_w + (size_t)(layer*HH + h)*NN*2;
    u64 wre2[4], wim2[4], nwim2[4];
    #pragma unroll
    for (int j = 0; j < 4; j++) {
        int base = (4*n2 + j) * 4;              // pair P = 4*n2+j holds n = 2P, 2P+1
        float r0 = wb[base],   i0 = wb[base+1];
        float r1 = wb[base+2], i1 = wb[base+3];
        wre2[j]  = pk2(r0, r1);
        wim2[j]  = pk2(i0, i1);
        nwim2[j] = pk2(-i0, -i1);
    }
    const u64 ZERO = 0ULL;

    // pass 1: chunk-local sums from zero state
    u64 sre[4] = {0,0,0,0}, sim[4] = {0,0,0,0};
    #pragma unroll 4
    for (int i = 0; i < 64; i++) {
        int t = dir ? (t0 + 64 - i) : (t0 + i);
        float u = su[t + (t >> 6)];
        u64 u2 = pk2(u, u);
        #pragma unroll
        for (int j = 0; j < 4; j++) {
            u64 tre = f2fma(wre2[j], sre[j], u2);
            tre     = f2fma(nwim2[j], sim[j], tre);
            u64 tim = f2fma(wim2[j], sre[j], ZERO);
            tim     = f2fma(wre2[j], sim[j], tim);
            sre[j] = tre; sim[j] = tim;
        }
    }
    {
        int s = ((dir*64 + chunk)*8 + 4*n2)*2;
        #pragma unroll
        for (int j = 0; j < 4; j++) { st[s + 2*j] = sre[j]; st[s + 2*j + 1] = sim[j]; }
    }
    __syncthreads();

    // combine: 16 threads, each one (dir, pair); in-place sums -> carries
    if (tid < 16) {
        int d = tid >> 3, P = tid & 7;
        int base = 4*P;
        float ra = wb[base], ia = wb[base+1], rb = wb[base+2], ib = wb[base+3];
        #pragma unroll
        for (int q = 0; q < 6; q++) {           // w^64
            float t1 = ra*ra - ia*ia; ia = 2.0f*ra*ia; ra = t1;
            float t2 = rb*rb - ib*ib; ib = 2.0f*rb*ib; rb = t2;
        }
        u64 Pre = pk2(ra, rb), Pim = pk2(ia, ib), nPim = pk2(-ia, -ib);
        u64 Fre = 0ULL, Fim = 0ULL;
        if (d == 0) {
            for (int c = 0; c < 64; c++) {
                int s = (c*8 + P)*2;
                u64 Sre = st[s], Sim = st[s+1];
                st[s] = Fre; st[s+1] = Fim;
                u64 t1 = f2fma(Pre, Fre, Sre);
                u64 nFre = f2fma(nPim, Fim, t1);
                u64 t2 = f2fma(Pre, Fim, Sim);
                u64 nFim = f2fma(Pim, Fre, t2);
                Fre = nFre; Fim = nFim;
            }
        } else {
            for (int c = 63; c >= 0; c--) {
                int s = ((64 + c)*8 + P)*2;
                u64 Sre = st[s], Sim = st[s+1];
                st[s] = Fre; st[s+1] = Fim;
                u64 t1 = f2fma(Pre, Fre, Sre);
                u64 nFre = f2fma(nPim, Fim, t1);
                u64 t2 = f2fma(Pre, Fim, Sim);
                u64 nFim = f2fma(Pim, Fre, t2);
                Fre = nFre; Fim = nFim;
            }
        }
    }
    __syncthreads();

    // load carries; pass-2-only emission constants loaded here
    {
        int s = ((dir*64 + chunk)*8 + 4*n2)*2;
        #pragma unroll
        for (int j = 0; j < 4; j++) { sre[j] = st[s + 2*j]; sim[j] = st[s + 2*j + 1]; }
    }
    const float* cb = g_ct + (size_t)((layer*2 + dir)*HH + h)*NN*2;
    u64 cre2[4], ncim2[4];
    #pragma unroll
    for (int j = 0; j < 4; j++) {
        int base = (4*n2 + j) * 4;
        cre2[j]  = pk2(cb[base], cb[base+2]);
        ncim2[j] = pk2(-cb[base+1], -cb[base+3]);
    }
    __syncthreads();

    // pass 2: full scan; emit with D*u folded at first touch
    float Dh = Din[layer*HH + h];
    #pragma unroll 4
    for (int i = 0; i < 64; i++) {
        int tout = dir ? (t0 + 63 - i) : (t0 + i);
        int tu   = tout + dir;                  // bwd consumes u[t+1]
        float u  = su[tu + (tu >> 6)];
        u64 u2 = pk2(u, u);
        u64 v2 = 0ULL;
        #pragma unroll
        for (int j = 0; j < 4; j++) {
            u64 tre = f2fma(wre2[j], sre[j], u2);
            tre     = f2fma(nwim2[j], sim[j], tre);
            u64 tim = f2fma(wim2[j], sre[j], ZERO);
            tim     = f2fma(wre2[j], sim[j], tim);
            sre[j] = tre; sim[j] = tim;
            v2 = f2fma(cre2[j], tre, v2);
            v2 = f2fma(ncim2[j], tim, v2);
        }
        float va, vb; upk2(v2, va, vb);
        float v = va + vb;
        v += __shfl_xor_sync(0xffffffffu, v, 1);    // partner n2
        if (n2 == 0) {
            int ts = tout + (tout >> 6);
            if (i < 32) sy[ts] = fmaf(Dh, su[ts], v);
            else        sy[ts] += v;
        }
    }
    __syncthreads();

    // epilogue: exact-erf GELU, fp16 hi/lo split, write (B,H,L)
    __half* oh = g_yh + (size_t)bh * LL;
    __half* ol = g_yl + (size_t)bh * LL;
    for (int t = tid; t < 4096; t += 256) {
        float v = sy[t + (t >> 6)];
        float g = 0.5f * v * (1.0f + erff(v * 0.70710678118f));
        __half hi = __float2half(g);
        oh[t] = hi;
        ol[t] = __float2half(g - __half2float(hi));
    }
}

// ---------------- fp16 HMMA GEMM: 3-stage ring, 1 barrier/iter ---------------
// CTA tile 128m x 128n (64 z0-cols + paired 64 z1-cols), 16 k-slices x 2 passes.
// Per iter: wait(ring) -> sync -> prefetch it+2 -> compute. Dynamic smem 55.5KB.
#define A_STG 8704
#define B_STG 10240
#define B_OFF (3*A_STG)
__global__ void __launch_bounds__(256) k_mma_glu(const float* __restrict__ out_b, int layer) {
    extern __shared__ __align__(16) char smraw[];
    int tid = threadIdx.x, warp = tid >> 5, lane = tid & 31;
    int wm = warp & 3, wn = warp >> 2;
    int n0 = blockIdx.x * 64;
    int m0 = blockIdx.y * 128;
    int b  = m0 >> 12;
    int l0 = m0 & 4095;
    uint32_t sbase = smem_u32(smraw);

    const __half* Wh = g_wh + (size_t)layer*2*HH*HH;

    float acc[2][8][4];
    #pragma unroll
    for (int a = 0; a < 2; a++)
        #pragma unroll
        for (int bb = 0; bb < 8; bb++)
            #pragma unroll
            for (int c = 0; c < 4; c++) acc[a][bb][c] = 0.f;

    // A loader: 512 chunks of 16B (32 k-rows x 16 chunks); 2 per thread
    int ar0 = tid >> 4,          ac0 = tid & 15;
    int ar1 = (tid + 256) >> 4,  ac1 = (tid + 256) & 15;
    // B loader: 512 chunks (128 n-rows x 4 chunks of 16B); 2 per thread
    int br0 = tid >> 2, bc0 = tid & 3;
    int br1 = br0 + 64, bc1 = bc0;
    int wr0 = (br0 < 64) ? (n0 + br0) : (448 + n0 + br0);
    int wr1 = (br1 < 64) ? (n0 + br1) : (448 + n0 + br1);

    int rl = lane & 7, q2 = (lane >> 3) & 1, q1 = lane >> 4;

    // it = slice*2 + sub; sub0: A=yh, sub1: A=yl; B loaded every it
    #define LOADT(it) do {                                                        \
        int it_ = (it);                                                           \
        int slot_ = it_ % 3;                                                      \
        int k0_ = (it_ >> 1) << 5;                                                \
        const __half* Y_ = ((it_ & 1) ? g_yl : g_yh) + (size_t)b*HH*LL;           \
        uint32_t Ab_ = sbase + slot_*A_STG;                                       \
        uint32_t Bb_ = sbase + B_OFF + slot_*B_STG;                               \
        cpa16(Ab_ + ar0*272 + ac0*16, Y_ + (size_t)(k0_ + ar0)*LL + l0 + ac0*8);  \
        cpa16(Ab_ + ar1*272 + ac1*16, Y_ + (size_t)(k0_ + ar1)*LL + l0 + ac1*8);  \
        cpa16(Bb_ + br0*80 + bc0*16, Wh + (size_t)wr0*HH + k0_ + bc0*8);          \
        cpa16(Bb_ + br1*80 + bc1*16, Wh + (size_t)wr1*HH + k0_ + bc1*8);          \
        asm volatile("cp.async.commit_group;");                                   \
    } while (0)

    LOADT(0);
    LOADT(1);
    for (int it = 0; it < 32; it++) {
        if (it < 31) asm volatile("cp.async.wait_group 1;");
        else         asm volatile("cp.async.wait_group 0;");
        __syncthreads();
        if (it + 2 < 32) LOADT(it + 2);

        int slot = it % 3;
        uint32_t Ab = sbase + slot*A_STG;
        uint32_t Bb = sbase + B_OFF + slot*B_STG;
        #pragma unroll
        for (int ks = 0; ks < 2; ks++) {
            int cb = ks << 4;                   // k16 block within the 32-k slice
            uint32_t a[2][4];
            #pragma unroll
            for (int mf = 0; mf < 2; mf++) {
                int krow = cb + (q1 << 3) + rl;
                uint32_t ad = Ab + krow*272 + ((wm << 5) + (mf << 4) + (q2 << 3))*2;
                asm volatile("ldmatrix.sync.aligned.m8n8.x4.trans.shared.b16 {%0,%1,%2,%3}, [%4];"
                             : "=r"(a[mf][0]), "=r"(a[mf][1]), "=r"(a[mf][2]), "=r"(a[mf][3])
                             : "r"(ad));
            }
            #pragma unroll
            for (int q = 0; q < 4; q++) {
                int nrow = (wn << 6) + (q << 4) + (q2 << 3) + rl;
                uint32_t bd = Bb + nrow*80 + ((ks << 1) + q1)*16;
                uint32_t b0, b1, b2, b3;
                asm volatile("ldmatrix.sync.aligned.m8n8.x4.shared.b16 {%0,%1,%2,%3}, [%4];"
                             : "=r"(b0), "=r"(b1), "=r"(b2), "=r"(b3) : "r"(bd));
                #pragma unroll
                for (int mf = 0; mf < 2; mf++) {
                    asm volatile("mma.sync.aligned.m16n8k16.row.col.f32.f16.f16.f32 "
                        "{%0,%1,%2,%3},{%4,%5,%6,%7},{%8,%9},{%0,%1,%2,%3};"
                        : "+f"(acc[mf][2*q][0]), "+f"(acc[mf][2*q][1]),
                          "+f"(acc[mf][2*q][2]), "+f"(acc[mf][2*q][3])
                        : "r"(a[mf][0]), "r"(a[mf][1]), "r"(a[mf][2]), "r"(a[mf][3]),
                          "r"(b0), "r"(b2));
                    asm volatile("mma.sync.aligned.m16n8k16.row.col.f32.f16.f16.f32 "
                        "{%0,%1,%2,%3},{%4,%5,%6,%7},{%8,%9},{%0,%1,%2,%3};"
                        : "+f"(acc[mf][2*q+1][0]), "+f"(acc[mf][2*q+1][1]),
                          "+f"(acc[mf][2*q+1][2]), "+f"(acc[mf][2*q+1][3])
                        : "r"(a[mf][0]), "r"(a[mf][1]), "r"(a[mf][2]), "r"(a[mf][3]),
                          "r"(b1), "r"(b3));
                }
            }
        }
    }
    #undef LOADT
    __syncthreads();

    // epilogue: z1 warps publish (z1+b1) via smem; z0 warps apply GLU + residual
    float* sb = (float*)smraw;
    const float* bias = out_b + (size_t)layer*1024 + n0;
    if (wn == 1) {
        #pragma unroll
        for (int mf = 0; mf < 2; mf++)
            #pragma unroll
            for (int nf = 0; nf < 8; nf++)
                #pragma unroll
                for (int r = 0; r < 4; r++) {
                    int row = mf*16 + (lane >> 2) + ((r >> 1) << 3);
                    int col = nf*8 + ((lane & 3) << 1) + (r & 1);
                    sb[(wm << 11) + (row << 6) + col] = acc[mf][nf][r] + bias[512 + col];
                }
    }
    __syncthreads();
    if (wn == 0) {
        #pragma unroll
        for (int mf = 0; mf < 2; mf++)
            #pragma unroll
            for (int nf = 0; nf < 8; nf++)
                #pragma unroll
                for (int r = 0; r < 4; r++) {
                    int row = mf*16 + (lane >> 2) + ((r >> 1) << 3);
                    int col = nf*8 + ((lane & 3) << 1) + (r & 1);
                    float z0 = acc[mf][nf][r] + bias[col];
                    float z1 = sb[(wm << 11) + (row << 6) + col];
                    float g  = z0 / (1.0f + expf(-z1));
                    g_h[(size_t)(m0 + wm*32 + row)*HH + n0 + col] += g;
                }
    }
}

// ---------------- decoder -----------------------------------------------------
__global__ void __launch_bounds__(256) k_decoder(const float* __restrict__ dec_w,
                                                 const float* __restrict__ dec_b,
                                                 float* __restrict__ out) {
    int row  = blockIdx.x*8 + (threadIdx.x >> 5);
    int lane = threadIdx.x & 31;
    const float* hr = g_h + (size_t)row*HH;
    float s = 0.f;
    #pragma unroll
    for (int j = 0; j < 16; j++) s = fmaf(hr[lane + 32*j], dec_w[lane + 32*j], s);
    #pragma unroll
    for (int o = 16; o > 0; o >>= 1) s += __shfl_xor_sync(0xffffffffu, s, o);
    if (lane == 0) out[row] = s + dec_b[0];
}

// ---------------- driver ------------------------------------------------------
extern "C" void kernel_launch(void* const* d_in, const int* in_sizes, int n_in,
                              void* d_out, int out_size) {
    const float* x      = (const float*)d_in[0];
    const float* enc_w  = (const float*)d_in[1];
    const float* enc_b  = (const float*)d_in[2];
    const float* log_dt = (const float*)d_in[3];
    const float* A_re   = (const float*)d_in[4];
    const float* A_im   = (const float*)d_in[5];
    const float* C_re   = (const float*)d_in[6];
    const float* C_im   = (const float*)d_in[7];
    const float* D      = (const float*)d_in[8];
    const float* out_w  = (const float*)d_in[9];
    const float* out_b  = (const float*)d_in[10];
    const float* ln_w   = (const float*)d_in[11];
    const float* ln_b   = (const float*)d_in[12];
    const float* dec_w  = (const float*)d_in[13];
    const float* dec_b  = (const float*)d_in[14];
    float* out = (float*)d_out;

    const int GEMM_SMEM = 3*A_STG + 3*B_STG;   // 56832
    cudaFuncSetAttribute(k_mma_glu, cudaFuncAttributeMaxDynamicSharedMemorySize, GEMM_SMEM);

    k_prep<<<(BB*LL*HH)/256, 256>>>(x, enc_w, enc_b, out_w,
                                    log_dt, A_re, A_im, C_re, C_im);

    for (int layer = 0; layer < NLAYERS; layer++) {
        dim3 lgrid(LL/32, BB);
        k_ln_t<<<lgrid, 256>>>(ln_w, ln_b, layer);
        k_scan<<<BB*HH, 256>>>(D, layer);
        dim3 ggrid(HH/64, (BB*LL)/128);
        k_mma_glu<<<ggrid, 256, GEMM_SMEM>>>(out_b, layer);
    }
    k_decoder<<<(BB*LL)/8, 256>>>(dec_w, dec_b, out);
}

// round 13
// speedup vs baseline: 1.1044x; 1.1044x over previous
#include <cuda_runtime.h>
#include <cuda_fp16.h>
#include <cstdint>

#define BB 8
#define LL 4096
#define HH 512
#define NN 16
#define NLAYERS 4

typedef unsigned long long u64;

__device__ __forceinline__ u64 pk2(float lo, float hi) {
    u64 r; asm("mov.b64 %0,{%1,%2};" : "=l"(r) : "f"(lo), "f"(hi)); return r;
}
__device__ __forceinline__ void upk2(u64 v, float& lo, float& hi) {
    asm("mov.b64 {%0,%1},%2;" : "=f"(lo), "=f"(hi) : "l"(v));
}
__device__ __forceinline__ u64 f2fma(u64 a, u64 b, u64 c) {
    u64 d; asm("fma.rn.f32x2 %0,%1,%2,%3;" : "=l"(d) : "l"(a), "l"(b), "l"(c)); return d;
}
__device__ __forceinline__ uint32_t smem_u32(const void* p) {
    uint32_t a;
    asm("{ .reg .u64 t; cvta.to.shared.u64 t, %1; cvt.u32.u64 %0, t; }" : "=r"(a) : "l"(p));
    return a;
}
__device__ __forceinline__ void cpa16(uint32_t dst, const void* src) {
    asm volatile("cp.async.cg.shared.global [%0],[%1],16;" :: "r"(dst), "l"(src));
}

// ---------------- scratch ----------------------------------------------------
__device__ float g_h [BB*LL*HH];
__device__ float g_ut[(size_t)BB*HH*LL];
__device__ float g_w [NLAYERS*HH*NN*2];
__device__ float g_ct[NLAYERS*2*HH*NN*2];
__device__ __half g_yh[(size_t)BB*HH*LL];   // (B,H,L) fp16 hi
__device__ __half g_yl[(size_t)BB*HH*LL];   // (B,H,L) fp16 lo
__device__ __half g_wh[NLAYERS*2*HH*HH];

// ---------------- prep: encoder + W->fp16 + SSM params, one kernel -----------
__global__ void k_prep(const float* __restrict__ x, const float* __restrict__ enc_w,
                       const float* __restrict__ enc_b, const float* __restrict__ out_w,
                       const float* __restrict__ log_dt, const float* __restrict__ A_re,
                       const float* __restrict__ A_im, const float* __restrict__ C_re,
                       const float* __restrict__ C_im) {
    int idx = blockIdx.x * blockDim.x + threadIdx.x;   // grid covers B*L*H
    int hh = idx % HH;
    int l  = (idx / HH) % LL;
    int b  = idx / (LL*HH);
    float grid = (float)l * (1.0f/(LL-1));
    g_h[idx] = enc_w[hh*2+0]*x[b*LL + l] + enc_w[hh*2+1]*grid + enc_b[hh];
    if (idx < NLAYERS*2*HH*HH) g_wh[idx] = __float2half(out_w[idx]);

    if (idx < NLAYERS*HH*NN) {
        int n     = idx % NN;
        int h     = (idx / NN) % HH;
        int layer = idx / (HH*NN);
        float dt  = expf(log_dt[layer*HH + h]);
        float are = A_re[idx];
        float aim = A_im[idx];
        float e   = expf(are*dt);
        float wre = e * cosf(aim*dt);
        float wim = e * sinf(aim*dt);
        g_w[idx*2+0] = wre;
        g_w[idx*2+1] = wim;
        float inv = 1.0f / (are*are + aim*aim);
        float nre = wre - 1.0f, nim = wim;
        float fre = (nre*are + nim*aim) * inv;
        float fim = (nim*are - nre*aim) * inv;
        #pragma unroll
        for (int c = 0; c < 2; c++) {
            int cidx = ((layer*2 + c)*HH + h)*NN + n;
            float cre = C_re[cidx], cim = C_im[cidx];
            g_ct[cidx*2+0] = 2.0f*(cre*fre - cim*fim);
            g_ct[cidx*2+1] = 2.0f*(cre*fim + cim*fre);
        }
    }
}

// ---------------- LayerNorm + transpose to (B,H,L) ---------------------------
__global__ void __launch_bounds__(256) k_ln_t(const float* __restrict__ ln_w,
                                              const float* __restrict__ ln_b, int layer) {
    __shared__ float s_mean[32], s_rstd[32];
    __shared__ float tile[64][33];
    int b  = blockIdx.y;
    int l0 = blockIdx.x * 32;
    int tid = threadIdx.x, warp = tid >> 5, lane = tid & 31;
    const float* lw = ln_w + layer*HH;
    const float* lb = ln_b + layer*HH;

    for (int r = warp; r < 32; r += 8) {
        const float4* row = (const float4*)(g_h + ((size_t)b*LL + l0 + r)*HH);
        float sum = 0.f, sq = 0.f;
        #pragma unroll
        for (int j = 0; j < 4; j++) {
            float4 v = row[lane + 32*j];
            sum += v.x + v.y + v.z + v.w;
            sq  += v.x*v.x + v.y*v.y + v.z*v.z + v.w*v.w;
        }
        #pragma unroll
        for (int o = 16; o > 0; o >>= 1) {
            sum += __shfl_xor_sync(0xffffffffu, sum, o);
            sq  += __shfl_xor_sync(0xffffffffu, sq , o);
        }
        if (lane == 0) {
            float mu = sum * (1.0f/HH);
            s_mean[r] = mu;
            s_rstd[r] = rsqrtf(sq * (1.0f/HH) - mu*mu + 1e-5f);
        }
    }
    __syncthreads();

    for (int h0 = 0; h0 < HH; h0 += 64) {
        #pragma unroll
        for (int p = 0; p < 8; p++) {
            int r = p*4 + (tid >> 6);
            int c = tid & 63;
            float v = g_h[((size_t)b*LL + l0 + r)*HH + h0 + c];
            tile[c][r] = (v - s_mean[r]) * s_rstd[r] * lw[h0 + c] + lb[h0 + c];
        }
        __syncthreads();
        #pragma unroll
        for (int p = 0; p < 8; p++) {
            int hh = p*8 + (tid >> 5);
            int lc = tid & 31;
            g_ut[((size_t)b*HH + h0 + hh)*LL + l0 + lc] = tile[hh][lc];
        }
        __syncthreads();
    }
}

// ---------------- bidirectional SSM scan: 8 modes/thread ---------------------
// 256 threads = 64 chunks(64 steps) x 2 dirs x 2 n-threads (8 n each, 4 pairs).
__global__ void __launch_bounds__(256, 3) k_scan(const float* __restrict__ Din, int layer) {
    __shared__ float su[4161];                  // skewed: idx = t + (t>>6)
    __shared__ __align__(8) char uni[16648];    // union: chunk-state (16KB) / sy
    u64*   st = (u64*)uni;
    float* sy = (float*)uni;

    int bh = blockIdx.x;
    int h  = bh & 511;
    int tid = threadIdx.x;
    const float* urow = g_ut + (size_t)bh * LL;

    for (int t = tid; t < 4096; t += 256) su[t + (t >> 6)] = urow[t];
    if (tid == 0) su[4160] = 0.0f;              // u[4096] = 0 pad
    __syncthreads();

    int n2    = tid & 1;                        // owns pairs P = 4*n2 + j
    int dir   = (tid >> 1) & 1;
    int chunk = tid >> 2;                       // 0..63
    int t0    = chunk << 6;

    const float* wb = g_w + (size_t)(layer*HH + h)*NN*2;
    u64 wre2[4], wim2[4], nwim2[4];
    #pragma unroll
    for (int j = 0; j < 4; j++) {
        int base = (4*n2 + j) * 4;              // pair P = 4*n2+j holds n = 2P, 2P+1
        float r0 = wb[base],   i0 = wb[base+1];
        float r1 = wb[base+2], i1 = wb[base+3];
        wre2[j]  = pk2(r0, r1);
        wim2[j]  = pk2(i0, i1);
        nwim2[j] = pk2(-i0, -i1);
    }
    const u64 ZERO = 0ULL;

    // pass 1: chunk-local sums from zero state
    u64 sre[4] = {0,0,0,0}, sim[4] = {0,0,0,0};
    #pragma unroll 4
    for (int i = 0; i < 64; i++) {
        int t = dir ? (t0 + 64 - i) : (t0 + i);
        float u = su[t + (t >> 6)];
        u64 u2 = pk2(u, u);
        #pragma unroll
        for (int j = 0; j < 4; j++) {
            u64 tre = f2fma(wre2[j], sre[j], u2);
            tre     = f2fma(nwim2[j], sim[j], tre);
            u64 tim = f2fma(wim2[j], sre[j], ZERO);
            tim     = f2fma(wre2[j], sim[j], tim);
            sre[j] = tre; sim[j] = tim;
        }
    }
    {
        int s = ((dir*64 + chunk)*8 + 4*n2)*2;
        #pragma unroll
        for (int j = 0; j < 4; j++) { st[s + 2*j] = sre[j]; st[s + 2*j + 1] = sim[j]; }
    }
    __syncthreads();

    // combine: 16 threads, each one (dir, pair); in-place sums -> carries
    if (tid < 16) {
        int d = tid >> 3, P = tid & 7;
        int base = 4*P;
        float ra = wb[base], ia = wb[base+1], rb = wb[base+2], ib = wb[base+3];
        #pragma unroll
        for (int q = 0; q < 6; q++) {           // w^64
            float t1 = ra*ra - ia*ia; ia = 2.0f*ra*ia; ra = t1;
            float t2 = rb*rb - ib*ib; ib = 2.0f*rb*ib; rb = t2;
        }
        u64 Pre = pk2(ra, rb), Pim = pk2(ia, ib), nPim = pk2(-ia, -ib);
        u64 Fre = 0ULL, Fim = 0ULL;
        if (d == 0) {
            for (int c = 0; c < 64; c++) {
                int s = (c*8 + P)*2;
                u64 Sre = st[s], Sim = st[s+1];
                st[s] = Fre; st[s+1] = Fim;
                u64 t1 = f2fma(Pre, Fre, Sre);
                u64 nFre = f2fma(nPim, Fim, t1);
                u64 t2 = f2fma(Pre, Fim, Sim);
                u64 nFim = f2fma(Pim, Fre, t2);
                Fre = nFre; Fim = nFim;
            }
        } else {
            for (int c = 63; c >= 0; c--) {
                int s = ((64 + c)*8 + P)*2;
                u64 Sre = st[s], Sim = st[s+1];
                st[s] = Fre; st[s+1] = Fim;
                u64 t1 = f2fma(Pre, Fre, Sre);
                u64 nFre = f2fma(nPim, Fim, t1);
                u64 t2 = f2fma(Pre, Fim, Sim);
                u64 nFim = f2fma(Pim, Fre, t2);
                Fre = nFre; Fim = nFim;
            }
        }
    }
    __syncthreads();

    // load carries; pass-2-only emission constants loaded here
    {
        int s = ((dir*64 + chunk)*8 + 4*n2)*2;
        #pragma unroll
        for (int j = 0; j < 4; j++) { sre[j] = st[s + 2*j]; sim[j] = st[s + 2*j + 1]; }
    }
    const float* cb = g_ct + (size_t)((layer*2 + dir)*HH + h)*NN*2;
    u64 cre2[4], ncim2[4];
    #pragma unroll
    for (int j = 0; j < 4; j++) {
        int base = (4*n2 + j) * 4;
        cre2[j]  = pk2(cb[base], cb[base+2]);
        ncim2[j] = pk2(-cb[base+1], -cb[base+3]);
    }
    __syncthreads();

    // pass 2: full scan; emit with D*u folded at first touch
    float Dh = Din[layer*HH + h];
    #pragma unroll 4
    for (int i = 0; i < 64; i++) {
        int tout = dir ? (t0 + 63 - i) : (t0 + i);
        int tu   = tout + dir;                  // bwd consumes u[t+1]
        float u  = su[tu + (tu >> 6)];
        u64 u2 = pk2(u, u);
        u64 v2 = 0ULL;
        #pragma unroll
        for (int j = 0; j < 4; j++) {
            u64 tre = f2fma(wre2[j], sre[j], u2);
            tre     = f2fma(nwim2[j], sim[j], tre);
            u64 tim = f2fma(wim2[j], sre[j], ZERO);
            tim     = f2fma(wre2[j], sim[j], tim);
            sre[j] = tre; sim[j] = tim;
            v2 = f2fma(cre2[j], tre, v2);
            v2 = f2fma(ncim2[j], tim, v2);
        }
        float va, vb; upk2(v2, va, vb);
        float v = va + vb;
        v += __shfl_xor_sync(0xffffffffu, v, 1);    // partner n2
        if (n2 == 0) {
            int ts = tout + (tout >> 6);
            if (i < 32) sy[ts] = fmaf(Dh, su[ts], v);
            else        sy[ts] += v;
        }
    }
    __syncthreads();

    // epilogue: exact-erf GELU, fp16 hi/lo split, write (B,H,L)
    __half* oh = g_yh + (size_t)bh * LL;
    __half* ol = g_yl + (size_t)bh * LL;
    for (int t = tid; t < 4096; t += 256) {
        float v = sy[t + (t >> 6)];
        float g = 0.5f * v * (1.0f + erff(v * 0.70710678118f));
        __half hi = __float2half(g);
        oh[t] = hi;
        ol[t] = __float2half(g - __half2float(hi));
    }
}

// ---------------- fp16 HMMA GEMM: 512 threads, warp tile 32x32 ---------------
// CTA tile 128m x 128n (64 z0-cols + paired 64 z1-cols), 16 k-slices x 2 passes.
// 16 warps as 4m x 4n; B loaded once per k-slice, reused by both A passes.
__global__ void __launch_bounds__(512, 2) k_mma_glu(const float* __restrict__ out_b, int layer) {
    __shared__ alignas(16) char smraw[37888];   // A: 2 x 8704 | B: 2 x 10240
    int tid = threadIdx.x, warp = tid >> 5, lane = tid & 31;
    int wm = warp & 3, wn = warp >> 2;          // wn 0..3; 0,1 = z0 cols, 2,3 = z1
    int n0 = blockIdx.x * 64;
    int m0 = blockIdx.y * 128;
    int b  = m0 >> 12;
    int l0 = m0 & 4095;
    uint32_t sbase = smem_u32(smraw);

    const __half* Wh = g_wh + (size_t)layer*2*HH*HH;

    float acc[2][4][4];                          // [mf][nf=2q+h8][r]
    #pragma unroll
    for (int a = 0; a < 2; a++)
        #pragma unroll
        for (int bb = 0; bb < 4; bb++)
            #pragma unroll
            for (int c = 0; c < 4; c++) acc[a][bb][c] = 0.f;

    // A loader: 512 chunks of 16B (32 k-rows x 16 chunks); 1 per thread
    int ar = tid >> 4, ac = tid & 15;
    // B loader: 512 chunks (128 n-rows x 4 chunks of 16B); 1 per thread
    int br = tid >> 2, bc = tid & 3;
    int wr = (br < 64) ? (n0 + br) : (448 + n0 + br);

    int rl = lane & 7, q2 = (lane >> 3) & 1, q1 = lane >> 4;

    // it = slice*2 + sub; sub0: A=yh (+ B load), sub1: A=yl (B reused)
    #define LOADT(it) do {                                                       \
        int it_ = (it);                                                          \
        int k0_ = (it_ >> 1) << 5;                                               \
        const __half* Y_ = ((it_ & 1) ? g_yl : g_yh) + (size_t)b*HH*LL;          \
        uint32_t Ab_ = sbase + (it_ & 1 ? 8704 : 0);                             \
        cpa16(Ab_ + ar*272 + ac*16, Y_ + (size_t)(k0_ + ar)*LL + l0 + ac*8);     \
        if ((it_ & 1) == 0) {                                                    \
            uint32_t Bb_ = sbase + 17408 + ((it_ >> 1) & 1) * 10240;             \
            cpa16(Bb_ + br*80 + bc*16, Wh + (size_t)wr*HH + k0_ + bc*8);         \
        }                                                                        \
        asm volatile("cp.async.commit_group;");                                  \
    } while (0)

    LOADT(0);
    for (int it = 0; it < 32; it++) {
        if (it + 1 < 32) {
            LOADT(it + 1);
            asm volatile("cp.async.wait_group 1;");
        } else {
            asm volatile("cp.async.wait_group 0;");
        }
        __syncthreads();

        uint32_t Ab = sbase + (it & 1 ? 8704 : 0);
        uint32_t Bb = sbase + 17408 + ((it >> 1) & 1) * 10240;
        #pragma unroll
        for (int ks = 0; ks < 2; ks++) {
            int cb = ks << 4;                   // k16 block within the 32-k slice
            uint32_t a[2][4];
            #pragma unroll
            for (int mf = 0; mf < 2; mf++) {
                int krow = cb + (q1 << 3) + rl;
                uint32_t ad = Ab + krow*272 + ((wm << 5) + (mf << 4) + (q2 << 3))*2;
                asm volatile("ldmatrix.sync.aligned.m8n8.x4.trans.shared.b16 {%0,%1,%2,%3}, [%4];"
                             : "=r"(a[mf][0]), "=r"(a[mf][1]), "=r"(a[mf][2]), "=r"(a[mf][3])
                             : "r"(ad));
            }
            #pragma unroll
            for (int q = 0; q < 2; q++) {
                int nrow = (wn << 5) + (q << 4) + (q2 << 3) + rl;
                uint32_t bd = Bb + nrow*80 + ((ks << 1) + q1)*16;
                uint32_t b0, b1, b2, b3;
                asm volatile("ldmatrix.sync.aligned.m8n8.x4.shared.b16 {%0,%1,%2,%3}, [%4];"
                             : "=r"(b0), "=r"(b1), "=r"(b2), "=r"(b3) : "r"(bd));
                #pragma unroll
                for (int mf = 0; mf < 2; mf++) {
                    asm volatile("mma.sync.aligned.m16n8k16.row.col.f32.f16.f16.f32 "
                        "{%0,%1,%2,%3},{%4,%5,%6,%7},{%8,%9},{%0,%1,%2,%3};"
                        : "+f"(acc[mf][2*q][0]), "+f"(acc[mf][2*q][1]),
                          "+f"(acc[mf][2*q][2]), "+f"(acc[mf][2*q][3])
                        : "r"(a[mf][0]), "r"(a[mf][1]), "r"(a[mf][2]), "r"(a[mf][3]),
                          "r"(b0), "r"(b2));
                    asm volatile("mma.sync.aligned.m16n8k16.row.col.f32.f16.f16.f32 "
                        "{%0,%1,%2,%3},{%4,%5,%6,%7},{%8,%9},{%0,%1,%2,%3};"
                        : "+f"(acc[mf][2*q+1][0]), "+f"(acc[mf][2*q+1][1]),
                          "+f"(acc[mf][2*q+1][2]), "+f"(acc[mf][2*q+1][3])
                        : "r"(a[mf][0]), "r"(a[mf][1]), "r"(a[mf][2]), "r"(a[mf][3]),
                          "r"(b1), "r"(b3));
                }
            }
        }
        __syncthreads();
    }
    #undef LOADT

    // epilogue: z1 warps (wn>=2) publish z1+b1 via smem; z0 warps apply GLU.
    // sb[(wm*32+row)*64 + col64], col64 = (wn%2)*32 + local col. 32KB < 37.8KB.
    float* sb = (float*)smraw;
    const float* bias = out_b + (size_t)layer*1024 + n0;
    if (wn >= 2) {
        #pragma unroll
        for (int mf = 0; mf < 2; mf++)
            #pragma unroll
            for (int nf = 0; nf < 4; nf++)
                #pragma unroll
                for (int r = 0; r < 4; r++) {
                    int row = mf*16 + (lane >> 2) + ((r >> 1) << 3);
                    int col = (nf >> 1)*16 + (nf & 1)*8 + ((lane & 3) << 1) + (r & 1);
                    int c64 = (wn - 2)*32 + col;
                    sb[(wm*32 + row)*64 + c64] = acc[mf][nf][r] + bias[512 + c64];
                }
    }
    __syncthreads();
    if (wn < 2) {
        #pragma unroll
        for (int mf = 0; mf < 2; mf++)
            #pragma unroll
            for (int nf = 0; nf < 4; nf++)
                #pragma unroll
                for (int r = 0; r < 4; r++) {
                    int row = mf*16 + (lane >> 2) + ((r >> 1) << 3);
                    int col = (nf >> 1)*16 + (nf & 1)*8 + ((lane & 3) << 1) + (r & 1);
                    int c64 = wn*32 + col;
                    float z0 = acc[mf][nf][r] + bias[c64];
                    float z1 = sb[(wm*32 + row)*64 + c64];
                    float g  = z0 / (1.0f + expf(-z1));
                    g_h[(size_t)(m0 + wm*32 + row)*HH + n0 + c64] += g;
                }
    }
}

// ---------------- decoder -----------------------------------------------------
__global__ void __launch_bounds__(256) k_decoder(const float* __restrict__ dec_w,
                                                 const float* __restrict__ dec_b,
                                                 float* __restrict__ out) {
    int row  = blockIdx.x*8 + (threadIdx.x >> 5);
    int lane = threadIdx.x & 31;
    const float* hr = g_h + (size_t)row*HH;
    float s = 0.f;
    #pragma unroll
    for (int j = 0; j < 16; j++) s = fmaf(hr[lane + 32*j], dec_w[lane + 32*j], s);
    #pragma unroll
    for (int o = 16; o > 0; o >>= 1) s += __shfl_xor_sync(0xffffffffu, s, o);
    if (lane == 0) out[row] = s + dec_b[0];
}

// ---------------- driver ------------------------------------------------------
extern "C" void kernel_launch(void* const* d_in, const int* in_sizes, int n_in,
                              void* d_out, int out_size) {
    const float* x      = (const float*)d_in[0];
    const float* enc_w  = (const float*)d_in[1];
    const float* enc_b  = (const float*)d_in[2];
    const float* log_dt = (const float*)d_in[3];
    const float* A_re   = (const float*)d_in[4];
    const float* A_im   = (const float*)d_in[5];
    const float* C_re   = (const float*)d_in[6];
    const float* C_im   = (const float*)d_in[7];
    const float* D      = (const float*)d_in[8];
    const float* out_w  = (const float*)d_in[9];
    const float* out_b  = (const float*)d_in[10];
    const float* ln_w   = (const float*)d_in[11];
    const float* ln_b   = (const float*)d_in[12];
    const float* dec_w  = (const float*)d_in[13];
    const float* dec_b  = (const float*)d_in[14];
    float* out = (float*)d_out;

    k_prep<<<(BB*LL*HH)/256, 256>>>(x, enc_w, enc_b, out_w,
                                    log_dt, A_re, A_im, C_re, C_im);

    for (int layer = 0; layer < NLAYERS; layer++) {
        dim3 lgrid(LL/32, BB);
        k_ln_t<<<lgrid, 256>>>(ln_w, ln_b, layer);
        k_scan<<<BB*HH, 256>>>(D, layer);
        dim3 ggrid(HH/64, (BB*LL)/128);
        k_mma_glu<<<ggrid, 512>>>(out_b, layer);
    }
    k_decoder<<<(BB*LL)/8, 256>>>(dec_w, dec_b, out);
}

// round 14
// speedup vs baseline: 1.1318x; 1.0247x over previous
#include <cuda_runtime.h>
#include <cuda_fp16.h>
#include <cstdint>

#define BB 8
#define LL 4096
#define HH 512
#define NN 16
#define NLAYERS 4

typedef unsigned long long u64;

__device__ __forceinline__ u64 pk2(float lo, float hi) {
    u64 r; asm("mov.b64 %0,{%1,%2};" : "=l"(r) : "f"(lo), "f"(hi)); return r;
}
__device__ __forceinline__ void upk2(u64 v, float& lo, float& hi) {
    asm("mov.b64 {%0,%1},%2;" : "=f"(lo), "=f"(hi) : "l"(v));
}
__device__ __forceinline__ u64 f2fma(u64 a, u64 b, u64 c) {
    u64 d; asm("fma.rn.f32x2 %0,%1,%2,%3;" : "=l"(d) : "l"(a), "l"(b), "l"(c)); return d;
}
__device__ __forceinline__ uint32_t smem_u32(const void* p) {
    uint32_t a;
    asm("{ .reg .u64 t; cvta.to.shared.u64 t, %1; cvt.u32.u64 %0, t; }" : "=r"(a) : "l"(p));
    return a;
}
__device__ __forceinline__ void cpa16(uint32_t dst, const void* src) {
    asm volatile("cp.async.cg.shared.global [%0],[%1],16;" :: "r"(dst), "l"(src));
}

// ---------------- scratch ----------------------------------------------------
__device__ float g_h [BB*LL*HH];
__device__ float g_ut[(size_t)BB*HH*LL];
__device__ float g_w [NLAYERS*HH*NN*2];
__device__ float g_ct[NLAYERS*2*HH*NN*2];
__device__ __half g_yh[(size_t)BB*HH*LL];   // (B,H,L) fp16 hi
__device__ __half g_yl[(size_t)BB*HH*LL];   // (B,H,L) fp16 lo
__device__ __half g_wh[NLAYERS*2*HH*HH];

// ---------------- prep: encoder + W->fp16 + SSM params, one kernel -----------
__global__ void k_prep(const float* __restrict__ x, const float* __restrict__ enc_w,
                       const float* __restrict__ enc_b, const float* __restrict__ out_w,
                       const float* __restrict__ log_dt, const float* __restrict__ A_re,
                       const float* __restrict__ A_im, const float* __restrict__ C_re,
                       const float* __restrict__ C_im) {
    int idx = blockIdx.x * blockDim.x + threadIdx.x;   // grid covers B*L*H
    int hh = idx % HH;
    int l  = (idx / HH) % LL;
    int b  = idx / (LL*HH);
    float grid = (float)l * (1.0f/(LL-1));
    g_h[idx] = enc_w[hh*2+0]*x[b*LL + l] + enc_w[hh*2+1]*grid + enc_b[hh];
    if (idx < NLAYERS*2*HH*HH) g_wh[idx] = __float2half(out_w[idx]);

    if (idx < NLAYERS*HH*NN) {
        int n     = idx % NN;
        int h     = (idx / NN) % HH;
        int layer = idx / (HH*NN);
        float dt  = expf(log_dt[layer*HH + h]);
        float are = A_re[idx];
        float aim = A_im[idx];
        float e   = expf(are*dt);
        float wre = e * cosf(aim*dt);
        float wim = e * sinf(aim*dt);
        g_w[idx*2+0] = wre;
        g_w[idx*2+1] = wim;
        float inv = 1.0f / (are*are + aim*aim);
        float nre = wre - 1.0f, nim = wim;
        float fre = (nre*are + nim*aim) * inv;
        float fim = (nim*are - nre*aim) * inv;
        #pragma unroll
        for (int c = 0; c < 2; c++) {
            int cidx = ((layer*2 + c)*HH + h)*NN + n;
            float cre = C_re[cidx], cim = C_im[cidx];
            g_ct[cidx*2+0] = 2.0f*(cre*fre - cim*fim);
            g_ct[cidx*2+1] = 2.0f*(cre*fim + cim*fre);
        }
    }
}

// ---------------- LayerNorm + transpose to (B,H,L) ---------------------------
__global__ void __launch_bounds__(256) k_ln_t(const float* __restrict__ ln_w,
                                              const float* __restrict__ ln_b, int layer) {
    __shared__ float s_mean[32], s_rstd[32];
    __shared__ float tile[64][33];
    int b  = blockIdx.y;
    int l0 = blockIdx.x * 32;
    int tid = threadIdx.x, warp = tid >> 5, lane = tid & 31;
    const float* lw = ln_w + layer*HH;
    const float* lb = ln_b + layer*HH;

    for (int r = warp; r < 32; r += 8) {
        const float4* row = (const float4*)(g_h + ((size_t)b*LL + l0 + r)*HH);
        float sum = 0.f, sq = 0.f;
        #pragma unroll
        for (int j = 0; j < 4; j++) {
            float4 v = row[lane + 32*j];
            sum += v.x + v.y + v.z + v.w;
            sq  += v.x*v.x + v.y*v.y + v.z*v.z + v.w*v.w;
        }
        #pragma unroll
        for (int o = 16; o > 0; o >>= 1) {
            sum += __shfl_xor_sync(0xffffffffu, sum, o);
            sq  += __shfl_xor_sync(0xffffffffu, sq , o);
        }
        if (lane == 0) {
            float mu = sum * (1.0f/HH);
            s_mean[r] = mu;
            s_rstd[r] = rsqrtf(sq * (1.0f/HH) - mu*mu + 1e-5f);
        }
    }
    __syncthreads();

    for (int h0 = 0; h0 < HH; h0 += 64) {
        #pragma unroll
        for (int p = 0; p < 8; p++) {
            int r = p*4 + (tid >> 6);
            int c = tid & 63;
            float v = g_h[((size_t)b*LL + l0 + r)*HH + h0 + c];
            tile[c][r] = (v - s_mean[r]) * s_rstd[r] * lw[h0 + c] + lb[h0 + c];
        }
        __syncthreads();
        #pragma unroll
        for (int p = 0; p < 8; p++) {
            int hh = p*8 + (tid >> 5);
            int lc = tid & 31;
            g_ut[((size_t)b*HH + h0 + hh)*LL + l0 + lc] = tile[hh][lc];
        }
        __syncthreads();
    }
}

// ---------------- bidirectional SSM scan: 8 modes/thread ---------------------
// 256 threads = 64 chunks(64 steps) x 2 dirs x 2 n-threads (8 n each, 4 pairs).
// launch_bounds(256,4): regs capped at 64 -> 4 CTAs/SM.
__global__ void __launch_bounds__(256, 4) k_scan(const float* __restrict__ Din, int layer) {
    __shared__ float su[4161];                  // skewed: idx = t + (t>>6)
    __shared__ __align__(8) char uni[16648];    // union: chunk-state (16KB) / sy
    u64*   st = (u64*)uni;
    float* sy = (float*)uni;

    int bh = blockIdx.x;
    int h  = bh & 511;
    int tid = threadIdx.x;
    const float* urow = g_ut + (size_t)bh * LL;

    for (int t = tid; t < 4096; t += 256) su[t + (t >> 6)] = urow[t];
    if (tid == 0) su[4160] = 0.0f;              // u[4096] = 0 pad
    __syncthreads();

    int n2    = tid & 1;                        // owns pairs P = 4*n2 + j
    int dir   = (tid >> 1) & 1;
    int chunk = tid >> 2;                       // 0..63
    int t0    = chunk << 6;

    const float* wb = g_w + (size_t)(layer*HH + h)*NN*2;
    u64 wre2[4], wim2[4], nwim2[4];
    #pragma unroll
    for (int j = 0; j < 4; j++) {
        int base = (4*n2 + j) * 4;              // pair P = 4*n2+j holds n = 2P, 2P+1
        float r0 = wb[base],   i0 = wb[base+1];
        float r1 = wb[base+2], i1 = wb[base+3];
        wre2[j]  = pk2(r0, r1);
        wim2[j]  = pk2(i0, i1);
        nwim2[j] = pk2(-i0, -i1);
    }
    const u64 ZERO = 0ULL;

    // pass 1: chunk-local sums from zero state
    u64 sre[4] = {0,0,0,0}, sim[4] = {0,0,0,0};
    #pragma unroll 4
    for (int i = 0; i < 64; i++) {
        int t = dir ? (t0 + 64 - i) : (t0 + i);
        float u = su[t + (t >> 6)];
        u64 u2 = pk2(u, u);
        #pragma unroll
        for (int j = 0; j < 4; j++) {
            u64 tre = f2fma(wre2[j], sre[j], u2);
            tre     = f2fma(nwim2[j], sim[j], tre);
            u64 tim = f2fma(wim2[j], sre[j], ZERO);
            tim     = f2fma(wre2[j], sim[j], tim);
            sre[j] = tre; sim[j] = tim;
        }
    }
    {
        int s = ((dir*64 + chunk)*8 + 4*n2)*2;
        #pragma unroll
        for (int j = 0; j < 4; j++) { st[s + 2*j] = sre[j]; st[s + 2*j + 1] = sim[j]; }
    }
    __syncthreads();

    // combine: 16 threads, each one (dir, pair); in-place sums -> carries
    if (tid < 16) {
        int d = tid >> 3, P = tid & 7;
        int base = 4*P;
        float ra = wb[base], ia = wb[base+1], rb = wb[base+2], ib = wb[base+3];
        #pragma unroll
        for (int q = 0; q < 6; q++) {           // w^64
            float t1 = ra*ra - ia*ia; ia = 2.0f*ra*ia; ra = t1;
            float t2 = rb*rb - ib*ib; ib = 2.0f*rb*ib; rb = t2;
        }
        u64 Pre = pk2(ra, rb), Pim = pk2(ia, ib), nPim = pk2(-ia, -ib);
        u64 Fre = 0ULL, Fim = 0ULL;
        if (d == 0) {
            for (int c = 0; c < 64; c++) {
                int s = (c*8 + P)*2;
                u64 Sre = st[s], Sim = st[s+1];
                st[s] = Fre; st[s+1] = Fim;
                u64 t1 = f2fma(Pre, Fre, Sre);
                u64 nFre = f2fma(nPim, Fim, t1);
                u64 t2 = f2fma(Pre, Fim, Sim);
                u64 nFim = f2fma(Pim, Fre, t2);
                Fre = nFre; Fim = nFim;
            }
        } else {
            for (int c = 63; c >= 0; c--) {
                int s = ((64 + c)*8 + P)*2;
                u64 Sre = st[s], Sim = st[s+1];
                st[s] = Fre; st[s+1] = Fim;
                u64 t1 = f2fma(Pre, Fre, Sre);
                u64 nFre = f2fma(nPim, Fim, t1);
                u64 t2 = f2fma(Pre, Fim, Sim);
                u64 nFim = f2fma(Pim, Fre, t2);
                Fre = nFre; Fim = nFim;
            }
        }
    }
    __syncthreads();

    // load carries; pass-2-only emission constants loaded here
    {
        int s = ((dir*64 + chunk)*8 + 4*n2)*2;
        #pragma unroll
        for (int j = 0; j < 4; j++) { sre[j] = st[s + 2*j]; sim[j] = st[s + 2*j + 1]; }
    }
    const float* cb = g_ct + (size_t)((layer*2 + dir)*HH + h)*NN*2;
    u64 cre2[4], ncim2[4];
    #pragma unroll
    for (int j = 0; j < 4; j++) {
        int base = (4*n2 + j) * 4;
        cre2[j]  = pk2(cb[base], cb[base+2]);
        ncim2[j] = pk2(-cb[base+1], -cb[base+3]);
    }
    __syncthreads();

    // pass 2: full scan; emit with D*u folded at first touch
    float Dh = Din[layer*HH + h];
    #pragma unroll 4
    for (int i = 0; i < 64; i++) {
        int tout = dir ? (t0 + 63 - i) : (t0 + i);
        int tu   = tout + dir;                  // bwd consumes u[t+1]
        float u  = su[tu + (tu >> 6)];
        u64 u2 = pk2(u, u);
        u64 v2 = 0ULL;
        #pragma unroll
        for (int j = 0; j < 4; j++) {
            u64 tre = f2fma(wre2[j], sre[j], u2);
            tre     = f2fma(nwim2[j], sim[j], tre);
            u64 tim = f2fma(wim2[j], sre[j], ZERO);
            tim     = f2fma(wre2[j], sim[j], tim);
            sre[j] = tre; sim[j] = tim;
            v2 = f2fma(cre2[j], tre, v2);
            v2 = f2fma(ncim2[j], tim, v2);
        }
        float va, vb; upk2(v2, va, vb);
        float v = va + vb;
        v += __shfl_xor_sync(0xffffffffu, v, 1);    // partner n2
        if (n2 == 0) {
            int ts = tout + (tout >> 6);
            if (i < 32) sy[ts] = fmaf(Dh, su[ts], v);
            else        sy[ts] += v;
        }
    }
    __syncthreads();

    // epilogue: exact-erf GELU, fp16 hi/lo split, write (B,H,L)
    __half* oh = g_yh + (size_t)bh * LL;
    __half* ol = g_yl + (size_t)bh * LL;
    for (int t = tid; t < 4096; t += 256) {
        float v = sy[t + (t >> 6)];
        float g = 0.5f * v * (1.0f + erff(v * 0.70710678118f));
        __half hi = __float2half(g);
        oh[t] = hi;
        ol[t] = __float2half(g - __half2float(hi));
    }
}

// ---------------- fp16 HMMA GEMM: 512 threads, A-ring-3/B-ring-2 -------------
// CTA tile 128m x 128n, 16 k-slices x 2 passes; ONE barrier per iteration.
// Static smem 46.6KB -> still 2 CTAs/SM (93KB < 228KB).
#define A_STG 8704
#define B_STG 10240
#define B_OFF (3*A_STG)
__global__ void __launch_bounds__(512, 2) k_mma_glu(const float* __restrict__ out_b, int layer) {
    __shared__ alignas(16) char smraw[3*A_STG + 2*B_STG];   // 46592
    int tid = threadIdx.x, warp = tid >> 5, lane = tid & 31;
    int wm = warp & 3, wn = warp >> 2;          // wn 0..3; 0,1 = z0 cols, 2,3 = z1
    int n0 = blockIdx.x * 64;
    int m0 = blockIdx.y * 128;
    int b  = m0 >> 12;
    int l0 = m0 & 4095;
    uint32_t sbase = smem_u32(smraw);

    const __half* Wh = g_wh + (size_t)layer*2*HH*HH;

    float acc[2][4][4];
    #pragma unroll
    for (int a = 0; a < 2; a++)
        #pragma unroll
        for (int bb = 0; bb < 4; bb++)
            #pragma unroll
            for (int c = 0; c < 4; c++) acc[a][bb][c] = 0.f;

    // A loader: 512 chunks of 16B (32 k-rows x 16 chunks); 1 per thread
    int ar = tid >> 4, ac = tid & 15;
    // B loader: 512 chunks (128 n-rows x 4 chunks of 16B); 1 per thread
    int br = tid >> 2, bc = tid & 3;
    int wr = (br < 64) ? (n0 + br) : (448 + n0 + br);

    int rl = lane & 7, q2 = (lane >> 3) & 1, q1 = lane >> 4;

    // it = slice*2 + sub; sub0: A=yh (+ B load), sub1: A=yl (B reused)
    #define LOADT(it) do {                                                       \
        int it_ = (it);                                                          \
        int k0_ = (it_ >> 1) << 5;                                               \
        const __half* Y_ = ((it_ & 1) ? g_yl : g_yh) + (size_t)b*HH*LL;          \
        uint32_t Ab_ = sbase + (it_ % 3)*A_STG;                                  \
        cpa16(Ab_ + ar*272 + ac*16, Y_ + (size_t)(k0_ + ar)*LL + l0 + ac*8);     \
        if ((it_ & 1) == 0) {                                                    \
            uint32_t Bb_ = sbase + B_OFF + ((it_ >> 1) & 1) * B_STG;             \
            cpa16(Bb_ + br*80 + bc*16, Wh + (size_t)wr*HH + k0_ + bc*8);         \
        }                                                                        \
        asm volatile("cp.async.commit_group;");                                  \
    } while (0)

    LOADT(0);
    LOADT(1);
    for (int it = 0; it < 32; it++) {
        if (it < 31) asm volatile("cp.async.wait_group 1;");
        else         asm volatile("cp.async.wait_group 0;");
        __syncthreads();
        if (it + 2 < 32) LOADT(it + 2);

        uint32_t Ab = sbase + (it % 3)*A_STG;
        uint32_t Bb = sbase + B_OFF + ((it >> 1) & 1)*B_STG;
        #pragma unroll
        for (int ks = 0; ks < 2; ks++) {
            int cb = ks << 4;                   // k16 block within the 32-k slice
            uint32_t a[2][4];
            #pragma unroll
            for (int mf = 0; mf < 2; mf++) {
                int krow = cb + (q1 << 3) + rl;
                uint32_t ad = Ab + krow*272 + ((wm << 5) + (mf << 4) + (q2 << 3))*2;
                asm volatile("ldmatrix.sync.aligned.m8n8.x4.trans.shared.b16 {%0,%1,%2,%3}, [%4];"
                             : "=r"(a[mf][0]), "=r"(a[mf][1]), "=r"(a[mf][2]), "=r"(a[mf][3])
                             : "r"(ad));
            }
            #pragma unroll
            for (int q = 0; q < 2; q++) {
                int nrow = (wn << 5) + (q << 4) + (q2 << 3) + rl;
                uint32_t bd = Bb + nrow*80 + ((ks << 1) + q1)*16;
                uint32_t b0, b1, b2, b3;
                asm volatile("ldmatrix.sync.aligned.m8n8.x4.shared.b16 {%0,%1,%2,%3}, [%4];"
                             : "=r"(b0), "=r"(b1), "=r"(b2), "=r"(b3) : "r"(bd));
                #pragma unroll
                for (int mf = 0; mf < 2; mf++) {
                    asm volatile("mma.sync.aligned.m16n8k16.row.col.f32.f16.f16.f32 "
                        "{%0,%1,%2,%3},{%4,%5,%6,%7},{%8,%9},{%0,%1,%2,%3};"
                        : "+f"(acc[mf][2*q][0]), "+f"(acc[mf][2*q][1]),
                          "+f"(acc[mf][2*q][2]), "+f"(acc[mf][2*q][3])
                        : "r"(a[mf][0]), "r"(a[mf][1]), "r"(a[mf][2]), "r"(a[mf][3]),
                          "r"(b0), "r"(b2));
                    asm volatile("mma.sync.aligned.m16n8k16.row.col.f32.f16.f16.f32 "
                        "{%0,%1,%2,%3},{%4,%5,%6,%7},{%8,%9},{%0,%1,%2,%3};"
                        : "+f"(acc[mf][2*q+1][0]), "+f"(acc[mf][2*q+1][1]),
                          "+f"(acc[mf][2*q+1][2]), "+f"(acc[mf][2*q+1][3])
                        : "r"(a[mf][0]), "r"(a[mf][1]), "r"(a[mf][2]), "r"(a[mf][3]),
                          "r"(b1), "r"(b3));
                }
            }
        }
    }
    #undef LOADT
    __syncthreads();

    // epilogue: z1 warps (wn>=2) publish z1+b1 via smem; z0 warps apply GLU.
    float* sb = (float*)smraw;
    const float* bias = out_b + (size_t)layer*1024 + n0;
    if (wn >= 2) {
        #pragma unroll
        for (int mf = 0; mf < 2; mf++)
            #pragma unroll
            for (int nf = 0; nf < 4; nf++)
                #pragma unroll
                for (int r = 0; r < 4; r++) {
                    int row = mf*16 + (lane >> 2) + ((r >> 1) << 3);
                    int col = (nf >> 1)*16 + (nf & 1)*8 + ((lane & 3) << 1) + (r & 1);
                    int c64 = (wn - 2)*32 + col;
                    sb[(wm*32 + row)*64 + c64] = acc[mf][nf][r] + bias[512 + c64];
                }
    }
    __syncthreads();
    if (wn < 2) {
        #pragma unroll
        for (int mf = 0; mf < 2; mf++)
            #pragma unroll
            for (int nf = 0; nf < 4; nf++)
                #pragma unroll
                for (int r = 0; r < 4; r++) {
                    int row = mf*16 + (lane >> 2) + ((r >> 1) << 3);
                    int col = (nf >> 1)*16 + (nf & 1)*8 + ((lane & 3) << 1) + (r & 1);
                    int c64 = wn*32 + col;
                    float z0 = acc[mf][nf][r] + bias[c64];
                    float z1 = sb[(wm*32 + row)*64 + c64];
                    float g  = z0 / (1.0f + expf(-z1));
                    g_h[(size_t)(m0 + wm*32 + row)*HH + n0 + c64] += g;
                }
    }
}

// ---------------- decoder -----------------------------------------------------
__global__ void __launch_bounds__(256) k_decoder(const float* __restrict__ dec_w,
                                                 const float* __restrict__ dec_b,
                                                 float* __restrict__ out) {
    int row  = blockIdx.x*8 + (threadIdx.x >> 5);
    int lane = threadIdx.x & 31;
    const float* hr = g_h + (size_t)row*HH;
    float s = 0.f;
    #pragma unroll
    for (int j = 0; j < 16; j++) s = fmaf(hr[lane + 32*j], dec_w[lane + 32*j], s);
    #pragma unroll
    for (int o = 16; o > 0; o >>= 1) s += __shfl_xor_sync(0xffffffffu, s, o);
    if (lane == 0) out[row] = s + dec_b[0];
}

// ---------------- driver ------------------------------------------------------
extern "C" void kernel_launch(void* const* d_in, const int* in_sizes, int n_in,
                              void* d_out, int out_size) {
    const float* x      = (const float*)d_in[0];
    const float* enc_w  = (const float*)d_in[1];
    const float* enc_b  = (const float*)d_in[2];
    const float* log_dt = (const float*)d_in[3];
    const float* A_re   = (const float*)d_in[4];
    const float* A_im   = (const float*)d_in[5];
    const float* C_re   = (const float*)d_in[6];
    const float* C_im   = (const float*)d_in[7];
    const float* D      = (const float*)d_in[8];
    const float* out_w  = (const float*)d_in[9];
    const float* out_b  = (const float*)d_in[10];
    const float* ln_w   = (const float*)d_in[11];
    const float* ln_b   = (const float*)d_in[12];
    const float* dec_w  = (const float*)d_in[13];
    const float* dec_b  = (const float*)d_in[14];
    float* out = (float*)d_out;

    k_prep<<<(BB*LL*HH)/256, 256>>>(x, enc_w, enc_b, out_w,
                                    log_dt, A_re, A_im, C_re, C_im);

    for (int layer = 0; layer < NLAYERS; layer++) {
        dim3 lgrid(LL/32, BB);
        k_ln_t<<<lgrid, 256>>>(ln_w, ln_b, layer);
        k_scan<<<BB*HH, 256>>>(D, layer);
        dim3 ggrid(HH/64, (BB*LL)/128);
        k_mma_glu<<<ggrid, 512>>>(out_b, layer);
    }
    k_decoder<<<(BB*LL)/8, 256>>>(dec_w, dec_b, out);
}

// round 15
// speedup vs baseline: 1.1337x; 1.0017x over previous
#include <cuda_runtime.h>
#include <cuda_fp16.h>
#include <cstdint>

#define BB 8
#define LL 4096
#define HH 512
#define NN 16
#define NLAYERS 4

typedef unsigned long long u64;

__device__ __forceinline__ u64 pk2(float lo, float hi) {
    u64 r; asm("mov.b64 %0,{%1,%2};" : "=l"(r) : "f"(lo), "f"(hi)); return r;
}
__device__ __forceinline__ void upk2(u64 v, float& lo, float& hi) {
    asm("mov.b64 {%0,%1},%2;" : "=f"(lo), "=f"(hi) : "l"(v));
}
__device__ __forceinline__ u64 f2fma(u64 a, u64 b, u64 c) {
    u64 d; asm("fma.rn.f32x2 %0,%1,%2,%3;" : "=l"(d) : "l"(a), "l"(b), "l"(c)); return d;
}
__device__ __forceinline__ uint32_t smem_u32(const void* p) {
    uint32_t a;
    asm("{ .reg .u64 t; cvta.to.shared.u64 t, %1; cvt.u32.u64 %0, t; }" : "=r"(a) : "l"(p));
    return a;
}
__device__ __forceinline__ void cpa16(uint32_t dst, const void* src) {
    asm volatile("cp.async.cg.shared.global [%0],[%1],16;" :: "r"(dst), "l"(src));
}

// ---------------- scratch ----------------------------------------------------
__device__ float g_h [BB*LL*HH];
__device__ float g_ut[(size_t)BB*HH*LL];
__device__ float g_w [NLAYERS*HH*NN*2];
__device__ float g_ct[NLAYERS*2*HH*NN*2];
__device__ __half g_yh[(size_t)BB*HH*LL];   // (B,H,L) fp16 hi
__device__ __half g_yl[(size_t)BB*HH*LL];   // (B,H,L) fp16 lo
__device__ __half g_wh[NLAYERS*2*HH*HH];

// ---------------- prep: encoder + W->fp16 + SSM params, one kernel -----------
__global__ void k_prep(const float* __restrict__ x, const float* __restrict__ enc_w,
                       const float* __restrict__ enc_b, const float* __restrict__ out_w,
                       const float* __restrict__ log_dt, const float* __restrict__ A_re,
                       const float* __restrict__ A_im, const float* __restrict__ C_re,
                       const float* __restrict__ C_im) {
    int idx = blockIdx.x * blockDim.x + threadIdx.x;   // grid covers B*L*H
    int hh = idx % HH;
    int l  = (idx / HH) % LL;
    int b  = idx / (LL*HH);
    float grid = (float)l * (1.0f/(LL-1));
    g_h[idx] = enc_w[hh*2+0]*x[b*LL + l] + enc_w[hh*2+1]*grid + enc_b[hh];
    if (idx < NLAYERS*2*HH*HH) g_wh[idx] = __float2half(out_w[idx]);

    if (idx < NLAYERS*HH*NN) {
        int n     = idx % NN;
        int h     = (idx / NN) % HH;
        int layer = idx / (HH*NN);
        float dt  = expf(log_dt[layer*HH + h]);
        float are = A_re[idx];
        float aim = A_im[idx];
        float e   = expf(are*dt);
        float wre = e * cosf(aim*dt);
        float wim = e * sinf(aim*dt);
        g_w[idx*2+0] = wre;
        g_w[idx*2+1] = wim;
        float inv = 1.0f / (are*are + aim*aim);
        float nre = wre - 1.0f, nim = wim;
        float fre = (nre*are + nim*aim) * inv;
        float fim = (nim*are - nre*aim) * inv;
        #pragma unroll
        for (int c = 0; c < 2; c++) {
            int cidx = ((layer*2 + c)*HH + h)*NN + n;
            float cre = C_re[cidx], cim = C_im[cidx];
            g_ct[cidx*2+0] = 2.0f*(cre*fre - cim*fim);
            g_ct[cidx*2+1] = 2.0f*(cre*fim + cim*fre);
        }
    }
}

// ---------------- LayerNorm + transpose to (B,H,L) ---------------------------
__global__ void __launch_bounds__(256) k_ln_t(const float* __restrict__ ln_w,
                                              const float* __restrict__ ln_b, int layer) {
    __shared__ float s_mean[32], s_rstd[32];
    __shared__ float tile[64][33];
    int b  = blockIdx.y;
    int l0 = blockIdx.x * 32;
    int tid = threadIdx.x, warp = tid >> 5, lane = tid & 31;
    const float* lw = ln_w + layer*HH;
    const float* lb = ln_b + layer*HH;

    for (int r = warp; r < 32; r += 8) {
        const float4* row = (const float4*)(g_h + ((size_t)b*LL + l0 + r)*HH);
        float sum = 0.f, sq = 0.f;
        #pragma unroll
        for (int j = 0; j < 4; j++) {
            float4 v = row[lane + 32*j];
            sum += v.x + v.y + v.z + v.w;
            sq  += v.x*v.x + v.y*v.y + v.z*v.z + v.w*v.w;
        }
        #pragma unroll
        for (int o = 16; o > 0; o >>= 1) {
            sum += __shfl_xor_sync(0xffffffffu, sum, o);
            sq  += __shfl_xor_sync(0xffffffffu, sq , o);
        }
        if (lane == 0) {
            float mu = sum * (1.0f/HH);
            s_mean[r] = mu;
            s_rstd[r] = rsqrtf(sq * (1.0f/HH) - mu*mu + 1e-5f);
        }
    }
    __syncthreads();

    for (int h0 = 0; h0 < HH; h0 += 64) {
        #pragma unroll
        for (int p = 0; p < 8; p++) {
            int r = p*4 + (tid >> 6);
            int c = tid & 63;
            float v = g_h[((size_t)b*LL + l0 + r)*HH + h0 + c];
            tile[c][r] = (v - s_mean[r]) * s_rstd[r] * lw[h0 + c] + lb[h0 + c];
        }
        __syncthreads();
        #pragma unroll
        for (int p = 0; p < 8; p++) {
            int hh = p*8 + (tid >> 5);
            int lc = tid & 31;
            g_ut[((size_t)b*HH + h0 + hh)*LL + l0 + lc] = tile[hh][lc];
        }
        __syncthreads();
    }
}

// ---------------- bidirectional SSM scan: 8 modes/thread ---------------------
// 256 threads = 64 chunks(64 steps) x 2 dirs x 2 n-threads (8 n each, 4 pairs).
__global__ void __launch_bounds__(256, 4) k_scan(const float* __restrict__ Din, int layer) {
    __shared__ float su[4161];                  // skewed: idx = t + (t>>6)
    __shared__ __align__(8) char uni[16648];    // union: chunk-state (16KB) / sy
    u64*   st = (u64*)uni;
    float* sy = (float*)uni;

    int bh = blockIdx.x;
    int h  = bh & 511;
    int tid = threadIdx.x;
    const float* urow = g_ut + (size_t)bh * LL;

    for (int t = tid; t < 4096; t += 256) su[t + (t >> 6)] = urow[t];
    if (tid == 0) su[4160] = 0.0f;              // u[4096] = 0 pad
    __syncthreads();

    int n2    = tid & 1;                        // owns pairs P = 4*n2 + j
    int dir   = (tid >> 1) & 1;
    int chunk = tid >> 2;                       // 0..63
    int t0    = chunk << 6;

    const float* wb = g_w + (size_t)(layer*HH + h)*NN*2;
    u64 wre2[4], wim2[4], nwim2[4];
    #pragma unroll
    for (int j = 0; j < 4; j++) {
        int base = (4*n2 + j) * 4;              // pair P = 4*n2+j holds n = 2P, 2P+1
        float r0 = wb[base],   i0 = wb[base+1];
        float r1 = wb[base+2], i1 = wb[base+3];
        wre2[j]  = pk2(r0, r1);
        wim2[j]  = pk2(i0, i1);
        nwim2[j] = pk2(-i0, -i1);
    }
    const u64 ZERO = 0ULL;

    // pass 1: chunk-local sums from zero state
    u64 sre[4] = {0,0,0,0}, sim[4] = {0,0,0,0};
    #pragma unroll 4
    for (int i = 0; i < 64; i++) {
        int t = dir ? (t0 + 64 - i) : (t0 + i);
        float u = su[t + (t >> 6)];
        u64 u2 = pk2(u, u);
        #pragma unroll
        for (int j = 0; j < 4; j++) {
            u64 tre = f2fma(wre2[j], sre[j], u2);
            tre     = f2fma(nwim2[j], sim[j], tre);
            u64 tim = f2fma(wim2[j], sre[j], ZERO);
            tim     = f2fma(wre2[j], sim[j], tim);
            sre[j] = tre; sim[j] = tim;
        }
    }
    {
        int s = ((dir*64 + chunk)*8 + 4*n2)*2;
        #pragma unroll
        for (int j = 0; j < 4; j++) { st[s + 2*j] = sre[j]; st[s + 2*j + 1] = sim[j]; }
    }
    __syncthreads();

    // combine: 16 threads, each one (dir, pair); in-place sums -> carries
    if (tid < 16) {
        int d = tid >> 3, P = tid & 7;
        int base = 4*P;
        float ra = wb[base], ia = wb[base+1], rb = wb[base+2], ib = wb[base+3];
        #pragma unroll
        for (int q = 0; q < 6; q++) {           // w^64
            float t1 = ra*ra - ia*ia; ia = 2.0f*ra*ia; ra = t1;
            float t2 = rb*rb - ib*ib; ib = 2.0f*rb*ib; rb = t2;
        }
        u64 Pre = pk2(ra, rb), Pim = pk2(ia, ib), nPim = pk2(-ia, -ib);
        u64 Fre = 0ULL, Fim = 0ULL;
        if (d == 0) {
            for (int c = 0; c < 64; c++) {
                int s = (c*8 + P)*2;
                u64 Sre = st[s], Sim = st[s+1];
                st[s] = Fre; st[s+1] = Fim;
                u64 t1 = f2fma(Pre, Fre, Sre);
                u64 nFre = f2fma(nPim, Fim, t1);
                u64 t2 = f2fma(Pre, Fim, Sim);
                u64 nFim = f2fma(Pim, Fre, t2);
                Fre = nFre; Fim = nFim;
            }
        } else {
            for (int c = 63; c >= 0; c--) {
                int s = ((64 + c)*8 + P)*2;
                u64 Sre = st[s], Sim = st[s+1];
                st[s] = Fre; st[s+1] = Fim;
                u64 t1 = f2fma(Pre, Fre, Sre);
                u64 nFre = f2fma(nPim, Fim, t1);
                u64 t2 = f2fma(Pre, Fim, Sim);
                u64 nFim = f2fma(Pim, Fre, t2);
                Fre = nFre; Fim = nFim;
            }
        }
    }
    __syncthreads();

    // load carries; pass-2-only emission constants loaded here
    {
        int s = ((dir*64 + chunk)*8 + 4*n2)*2;
        #pragma unroll
        for (int j = 0; j < 4; j++) { sre[j] = st[s + 2*j]; sim[j] = st[s + 2*j + 1]; }
    }
    const float* cb = g_ct + (size_t)((layer*2 + dir)*HH + h)*NN*2;
    u64 cre2[4], ncim2[4];
    #pragma unroll
    for (int j = 0; j < 4; j++) {
        int base = (4*n2 + j) * 4;
        cre2[j]  = pk2(cb[base], cb[base+2]);
        ncim2[j] = pk2(-cb[base+1], -cb[base+3]);
    }
    __syncthreads();

    // pass 2: full scan; emit with D*u folded at first touch
    float Dh = Din[layer*HH + h];
    #pragma unroll 4
    for (int i = 0; i < 64; i++) {
        int tout = dir ? (t0 + 63 - i) : (t0 + i);
        int tu   = tout + dir;                  // bwd consumes u[t+1]
        float u  = su[tu + (tu >> 6)];
        u64 u2 = pk2(u, u);
        u64 v2 = 0ULL;
        #pragma unroll
        for (int j = 0; j < 4; j++) {
            u64 tre = f2fma(wre2[j], sre[j], u2);
            tre     = f2fma(nwim2[j], sim[j], tre);
            u64 tim = f2fma(wim2[j], sre[j], ZERO);
            tim     = f2fma(wre2[j], sim[j], tim);
            sre[j] = tre; sim[j] = tim;
            v2 = f2fma(cre2[j], tre, v2);
            v2 = f2fma(ncim2[j], tim, v2);
        }
        float va, vb; upk2(v2, va, vb);
        float v = va + vb;
        v += __shfl_xor_sync(0xffffffffu, v, 1);    // partner n2
        if (n2 == 0) {
            int ts = tout + (tout >> 6);
            if (i < 32) sy[ts] = fmaf(Dh, su[ts], v);
            else        sy[ts] += v;
        }
    }
    __syncthreads();

    // epilogue: exact-erf GELU, fp16 hi/lo split, write (B,H,L)
    __half* oh = g_yh + (size_t)bh * LL;
    __half* ol = g_yl + (size_t)bh * LL;
    for (int t = tid; t < 4096; t += 256) {
        float v = sy[t + (t >> 6)];
        float g = 0.5f * v * (1.0f + erff(v * 0.70710678118f));
        __half hi = __float2half(g);
        oh[t] = hi;
        ol[t] = __float2half(g - __half2float(hi));
    }
}

// ---------------- fp16 HMMA GEMM: batched-LDSM inner loop --------------------
// CTA tile 128m x 128n, 16 k-slices x 2 passes; A-ring-3/B-ring-2, 1 barrier/it.
// Per k16: ALL 4 LDSM (A0,A1,B01) first, then all 16 MMAs (no interleaved stalls).
#define A_STG 8704
#define B_STG 10240
#define B_OFF (3*A_STG)
__global__ void __launch_bounds__(512, 2) k_mma_glu(const float* __restrict__ out_b, int layer) {
    __shared__ alignas(16) char smraw[3*A_STG + 2*B_STG];   // 46592
    int tid = threadIdx.x, warp = tid >> 5, lane = tid & 31;
    int wm = warp & 3, wn = warp >> 2;          // wn 0..3; 0,1 = z0 cols, 2,3 = z1
    int n0 = blockIdx.x * 64;
    int m0 = blockIdx.y * 128;
    int b  = m0 >> 12;
    int l0 = m0 & 4095;
    uint32_t sbase = smem_u32(smraw);

    const __half* Wh = g_wh + (size_t)layer*2*HH*HH;

    float acc[2][4][4];
    #pragma unroll
    for (int a = 0; a < 2; a++)
        #pragma unroll
        for (int bb = 0; bb < 4; bb++)
            #pragma unroll
            for (int c = 0; c < 4; c++) acc[a][bb][c] = 0.f;

    // A loader: 512 chunks of 16B (32 k-rows x 16 chunks); 1 per thread
    int ar = tid >> 4, ac = tid & 15;
    // B loader: 512 chunks (128 n-rows x 4 chunks of 16B); 1 per thread
    int br = tid >> 2, bc = tid & 3;
    int wr = (br < 64) ? (n0 + br) : (448 + n0 + br);

    int rl = lane & 7, q2 = (lane >> 3) & 1, q1 = lane >> 4;

    // it = slice*2 + sub; sub0: A=yh (+ B load), sub1: A=yl (B reused)
    #define LOADT(it) do {                                                       \
        int it_ = (it);                                                          \
        int k0_ = (it_ >> 1) << 5;                                               \
        const __half* Y_ = ((it_ & 1) ? g_yl : g_yh) + (size_t)b*HH*LL;          \
        uint32_t Ab_ = sbase + (it_ % 3)*A_STG;                                  \
        cpa16(Ab_ + ar*272 + ac*16, Y_ + (size_t)(k0_ + ar)*LL + l0 + ac*8);     \
        if ((it_ & 1) == 0) {                                                    \
            uint32_t Bb_ = sbase + B_OFF + ((it_ >> 1) & 1) * B_STG;             \
            cpa16(Bb_ + br*80 + bc*16, Wh + (size_t)wr*HH + k0_ + bc*8);         \
        }                                                                        \
        asm volatile("cp.async.commit_group;");                                  \
    } while (0)

    LOADT(0);
    LOADT(1);
    for (int it = 0; it < 32; it++) {
        if (it < 31) asm volatile("cp.async.wait_group 1;");
        else         asm volatile("cp.async.wait_group 0;");
        __syncthreads();
        if (it + 2 < 32) LOADT(it + 2);

        uint32_t Ab = sbase + (it % 3)*A_STG;
        uint32_t Bb = sbase + B_OFF + ((it >> 1) & 1)*B_STG;
        #pragma unroll
        for (int ks = 0; ks < 2; ks++) {
            int cb = ks << 4;                   // k16 block within the 32-k slice
            int krow = cb + (q1 << 3) + rl;
            uint32_t a[2][4], bfr[2][4];
            // batch ALL fragment loads first (LSU pipelines them)
            #pragma unroll
            for (int mf = 0; mf < 2; mf++) {
                uint32_t ad = Ab + krow*272 + ((wm << 5) + (mf << 4) + (q2 << 3))*2;
                asm volatile("ldmatrix.sync.aligned.m8n8.x4.trans.shared.b16 {%0,%1,%2,%3}, [%4];"
                             : "=r"(a[mf][0]), "=r"(a[mf][1]), "=r"(a[mf][2]), "=r"(a[mf][3])
                             : "r"(ad));
            }
            #pragma unroll
            for (int q = 0; q < 2; q++) {
                int nrow = (wn << 5) + (q << 4) + (q2 << 3) + rl;
                uint32_t bd = Bb + nrow*80 + ((ks << 1) + q1)*16;
                asm volatile("ldmatrix.sync.aligned.m8n8.x4.shared.b16 {%0,%1,%2,%3}, [%4];"
                             : "=r"(bfr[q][0]), "=r"(bfr[q][1]), "=r"(bfr[q][2]), "=r"(bfr[q][3])
                             : "r"(bd));
            }
            // then all 16 MMAs
            #pragma unroll
            for (int q = 0; q < 2; q++) {
                #pragma unroll
                for (int mf = 0; mf < 2; mf++) {
                    asm volatile("mma.sync.aligned.m16n8k16.row.col.f32.f16.f16.f32 "
                        "{%0,%1,%2,%3},{%4,%5,%6,%7},{%8,%9},{%0,%1,%2,%3};"
                        : "+f"(acc[mf][2*q][0]), "+f"(acc[mf][2*q][1]),
                          "+f"(acc[mf][2*q][2]), "+f"(acc[mf][2*q][3])
                        : "r"(a[mf][0]), "r"(a[mf][1]), "r"(a[mf][2]), "r"(a[mf][3]),
                          "r"(bfr[q][0]), "r"(bfr[q][2]));
                    asm volatile("mma.sync.aligned.m16n8k16.row.col.f32.f16.f16.f32 "
                        "{%0,%1,%2,%3},{%4,%5,%6,%7},{%8,%9},{%0,%1,%2,%3};"
                        : "+f"(acc[mf][2*q+1][0]), "+f"(acc[mf][2*q+1][1]),
                          "+f"(acc[mf][2*q+1][2]), "+f"(acc[mf][2*q+1][3])
                        : "r"(a[mf][0]), "r"(a[mf][1]), "r"(a[mf][2]), "r"(a[mf][3]),
                          "r"(bfr[q][1]), "r"(bfr[q][3]));
                }
            }
        }
    }
    #undef LOADT
    __syncthreads();

    // epilogue: z1 warps (wn>=2) publish z1+b1 via smem; z0 warps apply GLU.
    float* sb = (float*)smraw;
    const float* bias = out_b + (size_t)layer*1024 + n0;
    if (wn >= 2) {
        #pragma unroll
        for (int mf = 0; mf < 2; mf++)
            #pragma unroll
            for (int nf = 0; nf < 4; nf++)
                #pragma unroll
                for (int r = 0; r < 4; r++) {
                    int row = mf*16 + (lane >> 2) + ((r >> 1) << 3);
                    int col = (nf >> 1)*16 + (nf & 1)*8 + ((lane & 3) << 1) + (r & 1);
                    int c64 = (wn - 2)*32 + col;
                    sb[(wm*32 + row)*64 + c64] = acc[mf][nf][r] + bias[512 + c64];
                }
    }
    __syncthreads();
    if (wn < 2) {
        #pragma unroll
        for (int mf = 0; mf < 2; mf++)
            #pragma unroll
            for (int nf = 0; nf < 4; nf++)
                #pragma unroll
                for (int r = 0; r < 4; r++) {
                    int row = mf*16 + (lane >> 2) + ((r >> 1) << 3);
                    int col = (nf >> 1)*16 + (nf & 1)*8 + ((lane & 3) << 1) + (r & 1);
                    int c64 = wn*32 + col;
                    float z0 = acc[mf][nf][r] + bias[c64];
                    float z1 = sb[(wm*32 + row)*64 + c64];
                    float g  = z0 / (1.0f + expf(-z1));
                    g_h[(size_t)(m0 + wm*32 + row)*HH + n0 + c64] += g;
                }
    }
}

// ---------------- decoder -----------------------------------------------------
__global__ void __launch_bounds__(256) k_decoder(const float* __restrict__ dec_w,
                                                 const float* __restrict__ dec_b,
                                                 float* __restrict__ out) {
    int row  = blockIdx.x*8 + (threadIdx.x >> 5);
    int lane = threadIdx.x & 31;
    const float* hr = g_h + (size_t)row*HH;
    float s = 0.f;
    #pragma unroll
    for (int j = 0; j < 16; j++) s = fmaf(hr[lane + 32*j], dec_w[lane + 32*j], s);
    #pragma unroll
    for (int o = 16; o > 0; o >>= 1) s += __shfl_xor_sync(0xffffffffu, s, o);
    if (lane == 0) out[row] = s + dec_b[0];
}

// ---------------- driver ------------------------------------------------------
extern "C" void kernel_launch(void* const* d_in, const int* in_sizes, int n_in,
                              void* d_out, int out_size) {
    const float* x      = (const float*)d_in[0];
    const float* enc_w  = (const float*)d_in[1];
    const float* enc_b  = (const float*)d_in[2];
    const float* log_dt = (const float*)d_in[3];
    const float* A_re   = (const float*)d_in[4];
    const float* A_im   = (const float*)d_in[5];
    const float* C_re   = (const float*)d_in[6];
    const float* C_im   = (const float*)d_in[7];
    const float* D      = (const float*)d_in[8];
    const float* out_w  = (const float*)d_in[9];
    const float* out_b  = (const float*)d_in[10];
    const float* ln_w   = (const float*)d_in[11];
    const float* ln_b   = (const float*)d_in[12];
    const float* dec_w  = (const float*)d_in[13];
    const float* dec_b  = (const float*)d_in[14];
    float* out = (float*)d_out;

    k_prep<<<(BB*LL*HH)/256, 256>>>(x, enc_w, enc_b, out_w,
                                    log_dt, A_re, A_im, C_re, C_im);

    for (int layer = 0; layer < NLAYERS; layer++) {
        dim3 lgrid(LL/32, BB);
        k_ln_t<<<lgrid, 256>>>(ln_w, ln_b, layer);
        k_scan<<<BB*HH, 256>>>(D, layer);
        dim3 ggrid(HH/64, (BB*LL)/128);
        k_mma_glu<<<ggrid, 512>>>(out_b, layer);
    }
    k_decoder<<<(BB*LL)/8, 256>>>(dec_w, dec_b, out);
}

// round 16
// speedup vs baseline: 1.1568x; 1.0204x over previous
#include <cuda_runtime.h>
#include <cuda_fp16.h>
#include <cstdint>

#define BB 8
#define LL 4096
#define HH 512
#define NN 16
#define NLAYERS 4

typedef unsigned long long u64;

__device__ __forceinline__ u64 pk2(float lo, float hi) {
    u64 r; asm("mov.b64 %0,{%1,%2};" : "=l"(r) : "f"(lo), "f"(hi)); return r;
}
__device__ __forceinline__ void upk2(u64 v, float& lo, float& hi) {
    asm("mov.b64 {%0,%1},%2;" : "=f"(lo), "=f"(hi) : "l"(v));
}
__device__ __forceinline__ u64 f2fma(u64 a, u64 b, u64 c) {
    u64 d; asm("fma.rn.f32x2 %0,%1,%2,%3;" : "=l"(d) : "l"(a), "l"(b), "l"(c)); return d;
}
__device__ __forceinline__ uint32_t smem_u32(const void* p) {
    uint32_t a;
    asm("{ .reg .u64 t; cvta.to.shared.u64 t, %1; cvt.u32.u64 %0, t; }" : "=r"(a) : "l"(p));
    return a;
}
__device__ __forceinline__ void cpa16(uint32_t dst, const void* src) {
    asm volatile("cp.async.cg.shared.global [%0],[%1],16;" :: "r"(dst), "l"(src));
}

// ---------------- scratch ----------------------------------------------------
__device__ float g_h [BB*LL*HH];
__device__ float g_ut[(size_t)BB*HH*LL];
__device__ float g_w [NLAYERS*HH*NN*2];
__device__ float g_ct[NLAYERS*2*HH*NN*2];
__device__ __half g_yh[(size_t)BB*HH*LL];   // (B,H,L) fp16 hi
__device__ __half g_yl[(size_t)BB*HH*LL];   // (B,H,L) fp16 lo
__device__ __half g_wh[NLAYERS*2*HH*HH];

// ---------------- prep: encoder + W->fp16 + SSM params, one kernel -----------
__global__ void k_prep(const float* __restrict__ x, const float* __restrict__ enc_w,
                       const float* __restrict__ enc_b, const float* __restrict__ out_w,
                       const float* __restrict__ log_dt, const float* __restrict__ A_re,
                       const float* __restrict__ A_im, const float* __restrict__ C_re,
                       const float* __restrict__ C_im) {
    int idx = blockIdx.x * blockDim.x + threadIdx.x;   // grid covers B*L*H
    int hh = idx % HH;
    int l  = (idx / HH) % LL;
    int b  = idx / (LL*HH);
    float grid = (float)l * (1.0f/(LL-1));
    g_h[idx] = enc_w[hh*2+0]*x[b*LL + l] + enc_w[hh*2+1]*grid + enc_b[hh];
    if (idx < NLAYERS*2*HH*HH) g_wh[idx] = __float2half(out_w[idx]);

    if (idx < NLAYERS*HH*NN) {
        int n     = idx % NN;
        int h     = (idx / NN) % HH;
        int layer = idx / (HH*NN);
        float dt  = expf(log_dt[layer*HH + h]);
        float are = A_re[idx];
        float aim = A_im[idx];
        float e   = expf(are*dt);
        float wre = e * cosf(aim*dt);
        float wim = e * sinf(aim*dt);
        g_w[idx*2+0] = wre;
        g_w[idx*2+1] = wim;
        float inv = 1.0f / (are*are + aim*aim);
        float nre = wre - 1.0f, nim = wim;
        float fre = (nre*are + nim*aim) * inv;
        float fim = (nim*are - nre*aim) * inv;
        #pragma unroll
        for (int c = 0; c < 2; c++) {
            int cidx = ((layer*2 + c)*HH + h)*NN + n;
            float cre = C_re[cidx], cim = C_im[cidx];
            g_ct[cidx*2+0] = 2.0f*(cre*fre - cim*fim);
            g_ct[cidx*2+1] = 2.0f*(cre*fim + cim*fre);
        }
    }
}

// ---------------- LayerNorm + transpose to (B,H,L) ---------------------------
__global__ void __launch_bounds__(256) k_ln_t(const float* __restrict__ ln_w,
                                              const float* __restrict__ ln_b, int layer) {
    __shared__ float s_mean[32], s_rstd[32];
    __shared__ float tile[64][33];
    int b  = blockIdx.y;
    int l0 = blockIdx.x * 32;
    int tid = threadIdx.x, warp = tid >> 5, lane = tid & 31;
    const float* lw = ln_w + layer*HH;
    const float* lb = ln_b + layer*HH;

    for (int r = warp; r < 32; r += 8) {
        const float4* row = (const float4*)(g_h + ((size_t)b*LL + l0 + r)*HH);
        float sum = 0.f, sq = 0.f;
        #pragma unroll
        for (int j = 0; j < 4; j++) {
            float4 v = row[lane + 32*j];
            sum += v.x + v.y + v.z + v.w;
            sq  += v.x*v.x + v.y*v.y + v.z*v.z + v.w*v.w;
        }
        #pragma unroll
        for (int o = 16; o > 0; o >>= 1) {
            sum += __shfl_xor_sync(0xffffffffu, sum, o);
            sq  += __shfl_xor_sync(0xffffffffu, sq , o);
        }
        if (lane == 0) {
            float mu = sum * (1.0f/HH);
            s_mean[r] = mu;
            s_rstd[r] = rsqrtf(sq * (1.0f/HH) - mu*mu + 1e-5f);
        }
    }
    __syncthreads();

    for (int h0 = 0; h0 < HH; h0 += 64) {
        #pragma unroll
        for (int p = 0; p < 8; p++) {
            int r = p*4 + (tid >> 6);
            int c = tid & 63;
            float v = g_h[((size_t)b*LL + l0 + r)*HH + h0 + c];
            tile[c][r] = (v - s_mean[r]) * s_rstd[r] * lw[h0 + c] + lb[h0 + c];
        }
        __syncthreads();
        #pragma unroll
        for (int p = 0; p < 8; p++) {
            int hh = p*8 + (tid >> 5);
            int lc = tid & 31;
            g_ut[((size_t)b*HH + h0 + hh)*LL + l0 + lc] = tile[hh][lc];
        }
        __syncthreads();
    }
}

// ---------------- bidirectional SSM scan: 8 modes/thread ---------------------
// 256 threads = 64 chunks(64 steps) x 2 dirs x 2 n-threads (8 n each, 4 pairs).
__global__ void __launch_bounds__(256, 4) k_scan(const float* __restrict__ Din, int layer) {
    __shared__ float su[4161];                  // skewed: idx = t + (t>>6)
    __shared__ __align__(8) char uni[16648];    // union: chunk-state (16KB) / sy
    u64*   st = (u64*)uni;
    float* sy = (float*)uni;

    int bh = blockIdx.x;
    int h  = bh & 511;
    int tid = threadIdx.x;
    const float* urow = g_ut + (size_t)bh * LL;

    for (int t = tid; t < 4096; t += 256) su[t + (t >> 6)] = urow[t];
    if (tid == 0) su[4160] = 0.0f;              // u[4096] = 0 pad
    __syncthreads();

    int n2    = tid & 1;                        // owns pairs P = 4*n2 + j
    int dir   = (tid >> 1) & 1;
    int chunk = tid >> 2;                       // 0..63
    int t0    = chunk << 6;

    const float* wb = g_w + (size_t)(layer*HH + h)*NN*2;
    u64 wre2[4], wim2[4], nwim2[4];
    #pragma unroll
    for (int j = 0; j < 4; j++) {
        int base = (4*n2 + j) * 4;              // pair P = 4*n2+j holds n = 2P, 2P+1
        float r0 = wb[base],   i0 = wb[base+1];
        float r1 = wb[base+2], i1 = wb[base+3];
        wre2[j]  = pk2(r0, r1);
        wim2[j]  = pk2(i0, i1);
        nwim2[j] = pk2(-i0, -i1);
    }
    const u64 ZERO = 0ULL;

    // pass 1: chunk-local sums from zero state
    u64 sre[4] = {0,0,0,0}, sim[4] = {0,0,0,0};
    #pragma unroll 4
    for (int i = 0; i < 64; i++) {
        int t = dir ? (t0 + 64 - i) : (t0 + i);
        float u = su[t + (t >> 6)];
        u64 u2 = pk2(u, u);
        #pragma unroll
        for (int j = 0; j < 4; j++) {
            u64 tre = f2fma(wre2[j], sre[j], u2);
            tre     = f2fma(nwim2[j], sim[j], tre);
            u64 tim = f2fma(wim2[j], sre[j], ZERO);
            tim     = f2fma(wre2[j], sim[j], tim);
            sre[j] = tre; sim[j] = tim;
        }
    }
    {
        int s = ((dir*64 + chunk)*8 + 4*n2)*2;
        #pragma unroll
        for (int j = 0; j < 4; j++) { st[s + 2*j] = sre[j]; st[s + 2*j + 1] = sim[j]; }
    }
    __syncthreads();

    // combine: 16 threads, each one (dir, pair); in-place sums -> carries
    if (tid < 16) {
        int d = tid >> 3, P = tid & 7;
        int base = 4*P;
        float ra = wb[base], ia = wb[base+1], rb = wb[base+2], ib = wb[base+3];
        #pragma unroll
        for (int q = 0; q < 6; q++) {           // w^64
            float t1 = ra*ra - ia*ia; ia = 2.0f*ra*ia; ra = t1;
            float t2 = rb*rb - ib*ib; ib = 2.0f*rb*ib; rb = t2;
        }
        u64 Pre = pk2(ra, rb), Pim = pk2(ia, ib), nPim = pk2(-ia, -ib);
        u64 Fre = 0ULL, Fim = 0ULL;
        if (d == 0) {
            for (int c = 0; c < 64; c++) {
                int s = (c*8 + P)*2;
                u64 Sre = st[s], Sim = st[s+1];
                st[s] = Fre; st[s+1] = Fim;
                u64 t1 = f2fma(Pre, Fre, Sre);
                u64 nFre = f2fma(nPim, Fim, t1);
                u64 t2 = f2fma(Pre, Fim, Sim);
                u64 nFim = f2fma(Pim, Fre, t2);
                Fre = nFre; Fim = nFim;
            }
        } else {
            for (int c = 63; c >= 0; c--) {
                int s = ((64 + c)*8 + P)*2;
                u64 Sre = st[s], Sim = st[s+1];
                st[s] = Fre; st[s+1] = Fim;
                u64 t1 = f2fma(Pre, Fre, Sre);
                u64 nFre = f2fma(nPim, Fim, t1);
                u64 t2 = f2fma(Pre, Fim, Sim);
                u64 nFim = f2fma(Pim, Fre, t2);
                Fre = nFre; Fim = nFim;
            }
        }
    }
    __syncthreads();

    // load carries; pass-2-only emission constants loaded here
    {
        int s = ((dir*64 + chunk)*8 + 4*n2)*2;
        #pragma unroll
        for (int j = 0; j < 4; j++) { sre[j] = st[s + 2*j]; sim[j] = st[s + 2*j + 1]; }
    }
    const float* cb = g_ct + (size_t)((layer*2 + dir)*HH + h)*NN*2;
    u64 cre2[4], ncim2[4];
    #pragma unroll
    for (int j = 0; j < 4; j++) {
        int base = (4*n2 + j) * 4;
        cre2[j]  = pk2(cb[base], cb[base+2]);
        ncim2[j] = pk2(-cb[base+1], -cb[base+3]);
    }
    __syncthreads();

    // pass 2: full scan; emit with D*u folded at first touch
    float Dh = Din[layer*HH + h];
    #pragma unroll 4
    for (int i = 0; i < 64; i++) {
        int tout = dir ? (t0 + 63 - i) : (t0 + i);
        int tu   = tout + dir;                  // bwd consumes u[t+1]
        float u  = su[tu + (tu >> 6)];
        u64 u2 = pk2(u, u);
        u64 v2 = 0ULL;
        #pragma unroll
        for (int j = 0; j < 4; j++) {
            u64 tre = f2fma(wre2[j], sre[j], u2);
            tre     = f2fma(nwim2[j], sim[j], tre);
            u64 tim = f2fma(wim2[j], sre[j], ZERO);
            tim     = f2fma(wre2[j], sim[j], tim);
            sre[j] = tre; sim[j] = tim;
            v2 = f2fma(cre2[j], tre, v2);
            v2 = f2fma(ncim2[j], tim, v2);
        }
        float va, vb; upk2(v2, va, vb);
        float v = va + vb;
        v += __shfl_xor_sync(0xffffffffu, v, 1);    // partner n2
        if (n2 == 0) {
            int ts = tout + (tout >> 6);
            if (i < 32) sy[ts] = fmaf(Dh, su[ts], v);
            else        sy[ts] += v;
        }
    }
    __syncthreads();

    // epilogue: exact-erf GELU, fp16 hi/lo split, write (B,H,L)
    __half* oh = g_yh + (size_t)bh * LL;
    __half* ol = g_yl + (size_t)bh * LL;
    for (int t = tid; t < 4096; t += 256) {
        float v = sy[t + (t >> 6)];
        float g = 0.5f * v * (1.0f + erff(v * 0.70710678118f));
        __half hi = __float2half(g);
        oh[t] = hi;
        ol[t] = __float2half(g - __half2float(hi));
    }
}

// ---------------- fp16 HMMA GEMM: 64-k slices, 16 iterations -----------------
// CTA tile 128m x 128n, 8 k-slices(64k) x 2 passes; double-buffered dyn smem.
// Per iteration: 4 k16 blocks = 64 MMAs between barrier pairs.
#define A_STG 17408     // 64 k-rows x 272B
#define B_STG 18432     // 128 n-rows x 144B
#define B_OFF (2*A_STG)
__global__ void __launch_bounds__(512, 2) k_mma_glu(const float* __restrict__ out_b, int layer) {
    extern __shared__ __align__(16) char smraw[];
    int tid = threadIdx.x, warp = tid >> 5, lane = tid & 31;
    int wm = warp & 3, wn = warp >> 2;          // wn 0..3; 0,1 = z0 cols, 2,3 = z1
    int n0 = blockIdx.x * 64;
    int m0 = blockIdx.y * 128;
    int b  = m0 >> 12;
    int l0 = m0 & 4095;
    uint32_t sbase = smem_u32(smraw);

    const __half* Wh = g_wh + (size_t)layer*2*HH*HH;

    float acc[2][4][4];
    #pragma unroll
    for (int a = 0; a < 2; a++)
        #pragma unroll
        for (int bb = 0; bb < 4; bb++)
            #pragma unroll
            for (int c = 0; c < 4; c++) acc[a][bb][c] = 0.f;

    // A loader: 1024 chunks of 16B (64 k-rows x 16 chunks); 2 per thread
    int ar0 = tid >> 4, ac0 = tid & 15;
    int ar1 = ar0 + 32, ac1 = ac0;
    // B loader: 1024 chunks (128 n-rows x 8 chunks of 16B); 2 per thread
    int br0 = tid >> 3, bc0 = tid & 7;
    int br1 = br0 + 64, bc1 = bc0;
    int wr0 = (br0 < 64) ? (n0 + br0) : (448 + n0 + br0);
    int wr1 = (br1 < 64) ? (n0 + br1) : (448 + n0 + br1);

    int rl = lane & 7, q2 = (lane >> 3) & 1, q1 = lane >> 4;

    // it = slice*2 + sub; sub0: A=yh (+ B load), sub1: A=yl (B reused)
    #define LOADT(it) do {                                                       \
        int it_ = (it);                                                          \
        int k0_ = (it_ >> 1) << 6;                                               \
        const __half* Y_ = ((it_ & 1) ? g_yl : g_yh) + (size_t)b*HH*LL;          \
        uint32_t Ab_ = sbase + (it_ & 1)*A_STG;                                  \
        cpa16(Ab_ + ar0*272 + ac0*16, Y_ + (size_t)(k0_ + ar0)*LL + l0 + ac0*8); \
        cpa16(Ab_ + ar1*272 + ac1*16, Y_ + (size_t)(k0_ + ar1)*LL + l0 + ac1*8); \
        if ((it_ & 1) == 0) {                                                    \
            uint32_t Bb_ = sbase + B_OFF + ((it_ >> 1) & 1)*B_STG;               \
            cpa16(Bb_ + br0*144 + bc0*16, Wh + (size_t)wr0*HH + k0_ + bc0*8);    \
            cpa16(Bb_ + br1*144 + bc1*16, Wh + (size_t)wr1*HH + k0_ + bc1*8);    \
        }                                                                        \
        asm volatile("cp.async.commit_group;");                                  \
    } while (0)

    LOADT(0);
    for (int it = 0; it < 16; it++) {
        if (it + 1 < 16) {
            LOADT(it + 1);
            asm volatile("cp.async.wait_group 1;");
        } else {
            asm volatile("cp.async.wait_group 0;");
        }
        __syncthreads();

        uint32_t Ab = sbase + (it & 1)*A_STG;
        uint32_t Bb = sbase + B_OFF + ((it >> 1) & 1)*B_STG;
        #pragma unroll
        for (int ks = 0; ks < 4; ks++) {
            int krow = (ks << 4) + (q1 << 3) + rl;
            uint32_t a[2][4], bfr[2][4];
            #pragma unroll
            for (int mf = 0; mf < 2; mf++) {
                uint32_t ad = Ab + krow*272 + ((wm << 5) + (mf << 4) + (q2 << 3))*2;
                asm volatile("ldmatrix.sync.aligned.m8n8.x4.trans.shared.b16 {%0,%1,%2,%3}, [%4];"
                             : "=r"(a[mf][0]), "=r"(a[mf][1]), "=r"(a[mf][2]), "=r"(a[mf][3])
                             : "r"(ad));
            }
            #pragma unroll
            for (int q = 0; q < 2; q++) {
                int nrow = (wn << 5) + (q << 4) + (q2 << 3) + rl;
                uint32_t bd = Bb + nrow*144 + ((ks << 1) + q1)*16;
                asm volatile("ldmatrix.sync.aligned.m8n8.x4.shared.b16 {%0,%1,%2,%3}, [%4];"
                             : "=r"(bfr[q][0]), "=r"(bfr[q][1]), "=r"(bfr[q][2]), "=r"(bfr[q][3])
                             : "r"(bd));
            }
            #pragma unroll
            for (int q = 0; q < 2; q++) {
                #pragma unroll
                for (int mf = 0; mf < 2; mf++) {
                    asm volatile("mma.sync.aligned.m16n8k16.row.col.f32.f16.f16.f32 "
                        "{%0,%1,%2,%3},{%4,%5,%6,%7},{%8,%9},{%0,%1,%2,%3};"
                        : "+f"(acc[mf][2*q][0]), "+f"(acc[mf][2*q][1]),
                          "+f"(acc[mf][2*q][2]), "+f"(acc[mf][2*q][3])
                        : "r"(a[mf][0]), "r"(a[mf][1]), "r"(a[mf][2]), "r"(a[mf][3]),
                          "r"(bfr[q][0]), "r"(bfr[q][2]));
                    asm volatile("mma.sync.aligned.m16n8k16.row.col.f32.f16.f16.f32 "
                        "{%0,%1,%2,%3},{%4,%5,%6,%7},{%8,%9},{%0,%1,%2,%3};"
                        : "+f"(acc[mf][2*q+1][0]), "+f"(acc[mf][2*q+1][1]),
                          "+f"(acc[mf][2*q+1][2]), "+f"(acc[mf][2*q+1][3])
                        : "r"(a[mf][0]), "r"(a[mf][1]), "r"(a[mf][2]), "r"(a[mf][3]),
                          "r"(bfr[q][1]), "r"(bfr[q][3]));
                }
            }
        }
        __syncthreads();
    }
    #undef LOADT

    // epilogue: z1 warps (wn>=2) publish z1+b1 via smem; z0 warps apply GLU.
    float* sb = (float*)smraw;
    const float* bias = out_b + (size_t)layer*1024 + n0;
    if (wn >= 2) {
        #pragma unroll
        for (int mf = 0; mf < 2; mf++)
            #pragma unroll
            for (int nf = 0; nf < 4; nf++)
                #pragma unroll
                for (int r = 0; r < 4; r++) {
                    int row = mf*16 + (lane >> 2) + ((r >> 1) << 3);
                    int col = (nf >> 1)*16 + (nf & 1)*8 + ((lane & 3) << 1) + (r & 1);
                    int c64 = (wn - 2)*32 + col;
                    sb[(wm*32 + row)*64 + c64] = acc[mf][nf][r] + bias[512 + c64];
                }
    }
    __syncthreads();
    if (wn < 2) {
        #pragma unroll
        for (int mf = 0; mf < 2; mf++)
            #pragma unroll
            for (int nf = 0; nf < 4; nf++)
                #pragma unroll
                for (int r = 0; r < 4; r++) {
                    int row = mf*16 + (lane >> 2) + ((r >> 1) << 3);
                    int col = (nf >> 1)*16 + (nf & 1)*8 + ((lane & 3) << 1) + (r & 1);
                    int c64 = wn*32 + col;
                    float z0 = acc[mf][nf][r] + bias[c64];
                    float z1 = sb[(wm*32 + row)*64 + c64];
                    float g  = z0 / (1.0f + expf(-z1));
                    g_h[(size_t)(m0 + wm*32 + row)*HH + n0 + c64] += g;
                }
    }
}

// ---------------- decoder -----------------------------------------------------
__global__ void __launch_bounds__(256) k_decoder(const float* __restrict__ dec_w,
                                                 const float* __restrict__ dec_b,
                                                 float* __restrict__ out) {
    int row  = blockIdx.x*8 + (threadIdx.x >> 5);
    int lane = threadIdx.x & 31;
    const float* hr = g_h + (size_t)row*HH;
    float s = 0.f;
    #pragma unroll
    for (int j = 0; j < 16; j++) s = fmaf(hr[lane + 32*j], dec_w[lane + 32*j], s);
    #pragma unroll
    for (int o = 16; o > 0; o >>= 1) s += __shfl_xor_sync(0xffffffffu, s, o);
    if (lane == 0) out[row] = s + dec_b[0];
}

// ---------------- driver ------------------------------------------------------
extern "C" void kernel_launch(void* const* d_in, const int* in_sizes, int n_in,
                              void* d_out, int out_size) {
    const float* x      = (const float*)d_in[0];
    const float* enc_w  = (const float*)d_in[1];
    const float* enc_b  = (const float*)d_in[2];
    const float* log_dt = (const float*)d_in[3];
    const float* A_re   = (const float*)d_in[4];
    const float* A_im   = (const float*)d_in[5];
    const float* C_re   = (const float*)d_in[6];
    const float* C_im   = (const float*)d_in[7];
    const float* D      = (const float*)d_in[8];
    const float* out_w  = (const float*)d_in[9];
    const float* out_b  = (const float*)d_in[10];
    const float* ln_w   = (const float*)d_in[11];
    const float* ln_b   = (const float*)d_in[12];
    const float* dec_w  = (const float*)d_in[13];
    const float* dec_b  = (const float*)d_in[14];
    float* out = (float*)d_out;

    const int GEMM_SMEM = 2*A_STG + 2*B_STG;   // 71680
    cudaFuncSetAttribute(k_mma_glu, cudaFuncAttributeMaxDynamicSharedMemorySize, GEMM_SMEM);

    k_prep<<<(BB*LL*HH)/256, 256>>>(x, enc_w, enc_b, out_w,
                                    log_dt, A_re, A_im, C_re, C_im);

    for (int layer = 0; layer < NLAYERS; layer++) {
        dim3 lgrid(LL/32, BB);
        k_ln_t<<<lgrid, 256>>>(ln_w, ln_b, layer);
        k_scan<<<BB*HH, 256>>>(D, layer);
        dim3 ggrid(HH/64, (BB*LL)/128);
        k_mma_glu<<<ggrid, 512, GEMM_SMEM>>>(out_b, layer);
    }
    k_decoder<<<(BB*LL)/8, 256>>>(dec_w, dec_b, out);
}

// round 17
// speedup vs baseline: 1.1807x; 1.0206x over previous
#include <cuda_runtime.h>
#include <cuda_fp16.h>
#include <cstdint>

#define BB 8
#define LL 4096
#define HH 512
#define NN 16
#define NLAYERS 4

typedef unsigned long long u64;

__device__ __forceinline__ u64 pk2(float lo, float hi) {
    u64 r; asm("mov.b64 %0,{%1,%2};" : "=l"(r) : "f"(lo), "f"(hi)); return r;
}
__device__ __forceinline__ void upk2(u64 v, float& lo, float& hi) {
    asm("mov.b64 {%0,%1},%2;" : "=f"(lo), "=f"(hi) : "l"(v));
}
__device__ __forceinline__ u64 f2fma(u64 a, u64 b, u64 c) {
    u64 d; asm("fma.rn.f32x2 %0,%1,%2,%3;" : "=l"(d) : "l"(a), "l"(b), "l"(c)); return d;
}
__device__ __forceinline__ u64 f2add(u64 a, u64 b) {
    u64 d; asm("add.rn.f32x2 %0,%1,%2;" : "=l"(d) : "l"(a), "l"(b)); return d;
}
__device__ __forceinline__ uint32_t smem_u32(const void* p) {
    uint32_t a;
    asm("{ .reg .u64 t; cvta.to.shared.u64 t, %1; cvt.u32.u64 %0, t; }" : "=r"(a) : "l"(p));
    return a;
}
__device__ __forceinline__ void cpa16(uint32_t dst, const void* src) {
    asm volatile("cp.async.cg.shared.global [%0],[%1],16;" :: "r"(dst), "l"(src));
}

// ---------------- scratch ----------------------------------------------------
__device__ float g_h [BB*LL*HH];
__device__ float g_ut[(size_t)BB*HH*LL];
__device__ float g_w [NLAYERS*HH*NN*2];
__device__ float g_ct[NLAYERS*2*HH*NN*2];
__device__ __half g_yh[(size_t)BB*HH*LL];   // (B,H,L) fp16 hi
__device__ __half g_yl[(size_t)BB*HH*LL];   // (B,H,L) fp16 lo
__device__ __half g_wh[NLAYERS*2*HH*HH];

// ---------------- prep: encoder + W->fp16 + SSM params, one kernel -----------
__global__ void k_prep(const float* __restrict__ x, const float* __restrict__ enc_w,
                       const float* __restrict__ enc_b, const float* __restrict__ out_w,
                       const float* __restrict__ log_dt, const float* __restrict__ A_re,
                       const float* __restrict__ A_im, const float* __restrict__ C_re,
                       const float* __restrict__ C_im) {
    int idx = blockIdx.x * blockDim.x + threadIdx.x;   // grid covers B*L*H
    int hh = idx % HH;
    int l  = (idx / HH) % LL;
    int b  = idx / (LL*HH);
    float grid = (float)l * (1.0f/(LL-1));
    g_h[idx] = enc_w[hh*2+0]*x[b*LL + l] + enc_w[hh*2+1]*grid + enc_b[hh];
    if (idx < NLAYERS*2*HH*HH) g_wh[idx] = __float2half(out_w[idx]);

    if (idx < NLAYERS*HH*NN) {
        int n     = idx % NN;
        int h     = (idx / NN) % HH;
        int layer = idx / (HH*NN);
        float dt  = expf(log_dt[layer*HH + h]);
        float are = A_re[idx];
        float aim = A_im[idx];
        float e   = expf(are*dt);
        float wre = e * cosf(aim*dt);
        float wim = e * sinf(aim*dt);
        g_w[idx*2+0] = wre;
        g_w[idx*2+1] = wim;
        float inv = 1.0f / (are*are + aim*aim);
        float nre = wre - 1.0f, nim = wim;
        float fre = (nre*are + nim*aim) * inv;
        float fim = (nim*are - nre*aim) * inv;
        #pragma unroll
        for (int c = 0; c < 2; c++) {
            int cidx = ((layer*2 + c)*HH + h)*NN + n;
            float cre = C_re[cidx], cim = C_im[cidx];
            g_ct[cidx*2+0] = 2.0f*(cre*fre - cim*fim);
            g_ct[cidx*2+1] = 2.0f*(cre*fim + cim*fre);
        }
    }
}

// ---------------- LayerNorm + transpose to (B,H,L) ---------------------------
__global__ void __launch_bounds__(256) k_ln_t(const float* __restrict__ ln_w,
                                              const float* __restrict__ ln_b, int layer) {
    __shared__ float s_mean[32], s_rstd[32];
    __shared__ float tile[64][33];
    int b  = blockIdx.y;
    int l0 = blockIdx.x * 32;
    int tid = threadIdx.x, warp = tid >> 5, lane = tid & 31;
    const float* lw = ln_w + layer*HH;
    const float* lb = ln_b + layer*HH;

    for (int r = warp; r < 32; r += 8) {
        const float4* row = (const float4*)(g_h + ((size_t)b*LL + l0 + r)*HH);
        float sum = 0.f, sq = 0.f;
        #pragma unroll
        for (int j = 0; j < 4; j++) {
            float4 v = row[lane + 32*j];
            sum += v.x + v.y + v.z + v.w;
            sq  += v.x*v.x + v.y*v.y + v.z*v.z + v.w*v.w;
        }
        #pragma unroll
        for (int o = 16; o > 0; o >>= 1) {
            sum += __shfl_xor_sync(0xffffffffu, sum, o);
            sq  += __shfl_xor_sync(0xffffffffu, sq , o);
        }
        if (lane == 0) {
            float mu = sum * (1.0f/HH);
            s_mean[r] = mu;
            s_rstd[r] = rsqrtf(sq * (1.0f/HH) - mu*mu + 1e-5f);
        }
    }
    __syncthreads();

    for (int h0 = 0; h0 < HH; h0 += 64) {
        #pragma unroll
        for (int p = 0; p < 8; p++) {
            int r = p*4 + (tid >> 6);
            int c = tid & 63;
            float v = g_h[((size_t)b*LL + l0 + r)*HH + h0 + c];
            tile[c][r] = (v - s_mean[r]) * s_rstd[r] * lw[h0 + c] + lb[h0 + c];
        }
        __syncthreads();
        #pragma unroll
        for (int p = 0; p < 8; p++) {
            int hh = p*8 + (tid >> 5);
            int lc = tid & 31;
            g_ut[((size_t)b*HH + h0 + hh)*LL + l0 + lc] = tile[hh][lc];
        }
        __syncthreads();
    }
}

// ---------------- bidirectional SSM scan: 8 modes/thread ---------------------
// 256 threads = 64 chunks(64 steps) x 2 dirs x 2 n-threads (8 n each, 4 pairs).
__global__ void __launch_bounds__(256, 4) k_scan(const float* __restrict__ Din, int layer) {
    __shared__ float su[4161];                  // skewed: idx = t + (t>>6)
    __shared__ __align__(8) char uni[16648];    // union: chunk-state (16KB) / sy
    u64*   st = (u64*)uni;
    float* sy = (float*)uni;

    int bh = blockIdx.x;
    int h  = bh & 511;
    int tid = threadIdx.x;
    const float* urow = g_ut + (size_t)bh * LL;

    // vectorized su load: 4 x LDG.128 per thread; skew constant within 4-group
    for (int t4 = tid*4; t4 < 4096; t4 += 1024) {
        float4 v = *(const float4*)(urow + t4);
        int s = t4 + (t4 >> 6);
        su[s] = v.x; su[s+1] = v.y; su[s+2] = v.z; su[s+3] = v.w;
    }
    if (tid == 0) su[4160] = 0.0f;              // u[4096] = 0 pad
    __syncthreads();

    int n2    = tid & 1;                        // owns pairs P = 4*n2 + j
    int dir   = (tid >> 1) & 1;
    int chunk = tid >> 2;                       // 0..63
    int t0    = chunk << 6;

    const float* wb = g_w + (size_t)(layer*HH + h)*NN*2;
    u64 wre2[4], wim2[4], nwim2[4];
    #pragma unroll
    for (int j = 0; j < 4; j++) {
        int base = (4*n2 + j) * 4;              // pair P = 4*n2+j holds n = 2P, 2P+1
        float r0 = wb[base],   i0 = wb[base+1];
        float r1 = wb[base+2], i1 = wb[base+3];
        wre2[j]  = pk2(r0, r1);
        wim2[j]  = pk2(i0, i1);
        nwim2[j] = pk2(-i0, -i1);
    }
    const u64 ZERO = 0ULL;

    // pass 1: chunk-local sums from zero state
    u64 sre[4] = {0,0,0,0}, sim[4] = {0,0,0,0};
    #pragma unroll 4
    for (int i = 0; i < 64; i++) {
        int t = dir ? (t0 + 64 - i) : (t0 + i);
        float u = su[t + (t >> 6)];
        u64 u2 = pk2(u, u);
        #pragma unroll
        for (int j = 0; j < 4; j++) {
            u64 tre = f2fma(wre2[j], sre[j], u2);
            tre     = f2fma(nwim2[j], sim[j], tre);
            u64 tim = f2fma(wim2[j], sre[j], ZERO);
            tim     = f2fma(wre2[j], sim[j], tim);
            sre[j] = tre; sim[j] = tim;
        }
    }
    {
        int s = ((dir*64 + chunk)*8 + 4*n2)*2;
        #pragma unroll
        for (int j = 0; j < 4; j++) { st[s + 2*j] = sre[j]; st[s + 2*j + 1] = sim[j]; }
    }
    __syncthreads();

    // combine: 16 threads, each one (dir, pair); in-place sums -> carries
    if (tid < 16) {
        int d = tid >> 3, P = tid & 7;
        int base = 4*P;
        float ra = wb[base], ia = wb[base+1], rb = wb[base+2], ib = wb[base+3];
        #pragma unroll
        for (int q = 0; q < 6; q++) {           // w^64
            float t1 = ra*ra - ia*ia; ia = 2.0f*ra*ia; ra = t1;
            float t2 = rb*rb - ib*ib; ib = 2.0f*rb*ib; rb = t2;
        }
        u64 Pre = pk2(ra, rb), Pim = pk2(ia, ib), nPim = pk2(-ia, -ib);
        u64 Fre = 0ULL, Fim = 0ULL;
        if (d == 0) {
            for (int c = 0; c < 64; c++) {
                int s = (c*8 + P)*2;
                u64 Sre = st[s], Sim = st[s+1];
                st[s] = Fre; st[s+1] = Fim;
                u64 t1 = f2fma(Pre, Fre, Sre);
                u64 nFre = f2fma(nPim, Fim, t1);
                u64 t2 = f2fma(Pre, Fim, Sim);
                u64 nFim = f2fma(Pim, Fre, t2);
                Fre = nFre; Fim = nFim;
            }
        } else {
            for (int c = 63; c >= 0; c--) {
                int s = ((64 + c)*8 + P)*2;
                u64 Sre = st[s], Sim = st[s+1];
                st[s] = Fre; st[s+1] = Fim;
                u64 t1 = f2fma(Pre, Fre, Sre);
                u64 nFre = f2fma(nPim, Fim, t1);
                u64 t2 = f2fma(Pre, Fim, Sim);
                u64 nFim = f2fma(Pim, Fre, t2);
                Fre = nFre; Fim = nFim;
            }
        }
    }
    __syncthreads();

    // load carries; pass-2-only emission constants loaded here
    {
        int s = ((dir*64 + chunk)*8 + 4*n2)*2;
        #pragma unroll
        for (int j = 0; j < 4; j++) { sre[j] = st[s + 2*j]; sim[j] = st[s + 2*j + 1]; }
    }
    const float* cb = g_ct + (size_t)((layer*2 + dir)*HH + h)*NN*2;
    u64 cre2[4], ncim2[4];
    #pragma unroll
    for (int j = 0; j < 4; j++) {
        int base = (4*n2 + j) * 4;
        cre2[j]  = pk2(cb[base], cb[base+2]);
        ncim2[j] = pk2(-cb[base+1], -cb[base+3]);
    }
    __syncthreads();

    // pass 2: full scan; dual emission accumulators; D*u folded at first touch
    float Dh = Din[layer*HH + h];
    #pragma unroll 4
    for (int i = 0; i < 64; i++) {
        int tout = dir ? (t0 + 63 - i) : (t0 + i);
        int tu   = tout + dir;                  // bwd consumes u[t+1]
        float u  = su[tu + (tu >> 6)];
        u64 u2 = pk2(u, u);
        u64 va2 = 0ULL, vb2 = 0ULL;
        #pragma unroll
        for (int j = 0; j < 4; j++) {
            u64 tre = f2fma(wre2[j], sre[j], u2);
            tre     = f2fma(nwim2[j], sim[j], tre);
            u64 tim = f2fma(wim2[j], sre[j], ZERO);
            tim     = f2fma(wre2[j], sim[j], tim);
            sre[j] = tre; sim[j] = tim;
            if (j < 2) {
                va2 = f2fma(cre2[j], tre, va2);
                va2 = f2fma(ncim2[j], tim, va2);
            } else {
                vb2 = f2fma(cre2[j], tre, vb2);
                vb2 = f2fma(ncim2[j], tim, vb2);
            }
        }
        u64 v2 = f2add(va2, vb2);
        float va, vb; upk2(v2, va, vb);
        float v = va + vb;
        v += __shfl_xor_sync(0xffffffffu, v, 1);    // partner n2
        if (n2 == 0) {
            int ts = tout + (tout >> 6);
            if (i < 32) sy[ts] = fmaf(Dh, su[ts], v);
            else        sy[ts] += v;
        }
    }
    __syncthreads();

    // epilogue: exact-erf GELU, fp16 hi/lo split, half2 coalesced stores
    __half2* oh2 = (__half2*)(g_yh + (size_t)bh * LL);
    __half2* ol2 = (__half2*)(g_yl + (size_t)bh * LL);
    for (int p = tid; p < 2048; p += 256) {
        int t = p*2;                             // t even: same skew for t, t+1
        int s = t + (t >> 6);
        float v0 = sy[s], v1 = sy[s+1];
        float g0 = 0.5f * v0 * (1.0f + erff(v0 * 0.70710678118f));
        float g1 = 0.5f * v1 * (1.0f + erff(v1 * 0.70710678118f));
        __half h0 = __float2half(g0), h1 = __float2half(g1);
        oh2[p] = __halves2half2(h0, h1);
        ol2[p] = __halves2half2(__float2half(g0 - __half2float(h0)),
                                __float2half(g1 - __half2float(h1)));
    }
}

// ---------------- fp16 HMMA GEMM: 64-k slices, 16 iterations -----------------
#define A_STG 17408     // 64 k-rows x 272B
#define B_STG 18432     // 128 n-rows x 144B
#define B_OFF (2*A_STG)
__global__ void __launch_bounds__(512, 2) k_mma_glu(const float* __restrict__ out_b, int layer) {
    extern __shared__ __align__(16) char smraw[];
    int tid = threadIdx.x, warp = tid >> 5, lane = tid & 31;
    int wm = warp & 3, wn = warp >> 2;          // wn 0..3; 0,1 = z0 cols, 2,3 = z1
    int n0 = blockIdx.x * 64;
    int m0 = blockIdx.y * 128;
    int b  = m0 >> 12;
    int l0 = m0 & 4095;
    uint32_t sbase = smem_u32(smraw);

    const __half* Wh = g_wh + (size_t)layer*2*HH*HH;

    float acc[2][4][4];
    #pragma unroll
    for (int a = 0; a < 2; a++)
        #pragma unroll
        for (int bb = 0; bb < 4; bb++)
            #pragma unroll
            for (int c = 0; c < 4; c++) acc[a][bb][c] = 0.f;

    // A loader: 1024 chunks of 16B (64 k-rows x 16 chunks); 2 per thread
    int ar0 = tid >> 4, ac0 = tid & 15;
    int ar1 = ar0 + 32, ac1 = ac0;
    // B loader: 1024 chunks (128 n-rows x 8 chunks of 16B); 2 per thread
    int br0 = tid >> 3, bc0 = tid & 7;
    int br1 = br0 + 64, bc1 = bc0;
    int wr0 = (br0 < 64) ? (n0 + br0) : (448 + n0 + br0);
    int wr1 = (br1 < 64) ? (n0 + br1) : (448 + n0 + br1);

    int rl = lane & 7, q2 = (lane >> 3) & 1, q1 = lane >> 4;
    // hoisted LDSM base offsets (iteration-invariant)
    uint32_t aBaseT = (uint32_t)(((q1 << 3) + rl)*272 + ((wm << 5) + (q2 << 3))*2);
    uint32_t bBaseT = (uint32_t)(((wn << 5) + (q2 << 3) + rl)*144 + q1*16);

    // it = slice*2 + sub; sub0: A=yh (+ B load), sub1: A=yl (B reused)
    #define LOADT(it) do {                                                       \
        int it_ = (it);                                                          \
        int k0_ = (it_ >> 1) << 6;                                               \
        const __half* Y_ = ((it_ & 1) ? g_yl : g_yh) + (size_t)b*HH*LL;          \
        uint32_t Ab_ = sbase + (it_ & 1)*A_STG;                                  \
        cpa16(Ab_ + ar0*272 + ac0*16, Y_ + (size_t)(k0_ + ar0)*LL + l0 + ac0*8); \
        cpa16(Ab_ + ar1*272 + ac1*16, Y_ + (size_t)(k0_ + ar1)*LL + l0 + ac1*8); \
        if ((it_ & 1) == 0) {                                                    \
            uint32_t Bb_ = sbase + B_OFF + ((it_ >> 1) & 1)*B_STG;               \
            cpa16(Bb_ + br0*144 + bc0*16, Wh + (size_t)wr0*HH + k0_ + bc0*8);    \
            cpa16(Bb_ + br1*144 + bc1*16, Wh + (size_t)wr1*HH + k0_ + bc1*8);    \
        }                                                                        \
        asm volatile("cp.async.commit_group;");                                  \
    } while (0)

    LOADT(0);
    for (int it = 0; it < 16; it++) {
        if (it + 1 < 16) {
            LOADT(it + 1);
            asm volatile("cp.async.wait_group 1;");
        } else {
            asm volatile("cp.async.wait_group 0;");
        }
        __syncthreads();

        uint32_t Abase = sbase + (it & 1)*A_STG + aBaseT;
        uint32_t Bbase = sbase + B_OFF + ((it >> 1) & 1)*B_STG + bBaseT;
        #pragma unroll
        for (int ks = 0; ks < 4; ks++) {
            uint32_t a[2][4], bfr[2][4];
            #pragma unroll
            for (int mf = 0; mf < 2; mf++) {
                uint32_t ad = Abase + ks*4352 + mf*32;
                asm volatile("ldmatrix.sync.aligned.m8n8.x4.trans.shared.b16 {%0,%1,%2,%3}, [%4];"
                             : "=r"(a[mf][0]), "=r"(a[mf][1]), "=r"(a[mf][2]), "=r"(a[mf][3])
                             : "r"(ad));
            }
            #pragma unroll
            for (int q = 0; q < 2; q++) {
                uint32_t bd = Bbase + q*2304 + ks*32;
                asm volatile("ldmatrix.sync.aligned.m8n8.x4.shared.b16 {%0,%1,%2,%3}, [%4];"
                             : "=r"(bfr[q][0]), "=r"(bfr[q][1]), "=r"(bfr[q][2]), "=r"(bfr[q][3])
                             : "r"(bd));
            }
            #pragma unroll
            for (int q = 0; q < 2; q++) {
                #pragma unroll
                for (int mf = 0; mf < 2; mf++) {
                    asm volatile("mma.sync.aligned.m16n8k16.row.col.f32.f16.f16.f32 "
                        "{%0,%1,%2,%3},{%4,%5,%6,%7},{%8,%9},{%0,%1,%2,%3};"
                        : "+f"(acc[mf][2*q][0]), "+f"(acc[mf][2*q][1]),
                          "+f"(acc[mf][2*q][2]), "+f"(acc[mf][2*q][3])
                        : "r"(a[mf][0]), "r"(a[mf][1]), "r"(a[mf][2]), "r"(a[mf][3]),
                          "r"(bfr[q][0]), "r"(bfr[q][2]));
                    asm volatile("mma.sync.aligned.m16n8k16.row.col.f32.f16.f16.f32 "
                        "{%0,%1,%2,%3},{%4,%5,%6,%7},{%8,%9},{%0,%1,%2,%3};"
                        : "+f"(acc[mf][2*q+1][0]), "+f"(acc[mf][2*q+1][1]),
                          "+f"(acc[mf][2*q+1][2]), "+f"(acc[mf][2*q+1][3])
                        : "r"(a[mf][0]), "r"(a[mf][1]), "r"(a[mf][2]), "r"(a[mf][3]),
                          "r"(bfr[q][1]), "r"(bfr[q][3]));
                }
            }
        }
        __syncthreads();
    }
    #undef LOADT

    // epilogue: z1 warps (wn>=2) publish z1+b1 via smem; z0 warps apply GLU.
    float* sb = (float*)smraw;
    const float* bias = out_b + (size_t)layer*1024 + n0;
    if (wn >= 2) {
        #pragma unroll
        for (int mf = 0; mf < 2; mf++)
            #pragma unroll
            for (int nf = 0; nf < 4; nf++)
                #pragma unroll
                for (int r = 0; r < 4; r++) {
                    int row = mf*16 + (lane >> 2) + ((r >> 1) << 3);
                    int col = (nf >> 1)*16 + (nf & 1)*8 + ((lane & 3) << 1) + (r & 1);
                    int c64 = (wn - 2)*32 + col;
                    sb[(wm*32 + row)*64 + c64] = acc[mf][nf][r] + bias[512 + c64];
                }
    }
    __syncthreads();
    if (wn < 2) {
        #pragma unroll
        for (int mf = 0; mf < 2; mf++)
            #pragma unroll
            for (int nf = 0; nf < 4; nf++)
                #pragma unroll
                for (int r = 0; r < 4; r++) {
                    int row = mf*16 + (lane >> 2) + ((r >> 1) << 3);
                    int col = (nf >> 1)*16 + (nf & 1)*8 + ((lane & 3) << 1) + (r & 1);
                    int c64 = wn*32 + col;
                    float z0 = acc[mf][nf][r] + bias[c64];
                    float z1 = sb[(wm*32 + row)*64 + c64];
                    float g  = z0 / (1.0f + expf(-z1));
                    g_h[(size_t)(m0 + wm*32 + row)*HH + n0 + c64] += g;
                }
    }
}

// ---------------- decoder -----------------------------------------------------
__global__ void __launch_bounds__(256) k_decoder(const float* __restrict__ dec_w,
                                                 const float* __restrict__ dec_b,
                                                 float* __restrict__ out) {
    int row  = blockIdx.x*8 + (threadIdx.x >> 5);
    int lane = threadIdx.x & 31;
    const float* hr = g_h + (size_t)row*HH;
    float s = 0.f;
    #pragma unroll
    for (int j = 0; j < 16; j++) s = fmaf(hr[lane + 32*j], dec_w[lane + 32*j], s);
    #pragma unroll
    for (int o = 16; o > 0; o >>= 1) s += __shfl_xor_sync(0xffffffffu, s, o);
    if (lane == 0) out[row] = s + dec_b[0];
}

// ---------------- driver ------------------------------------------------------
extern "C" void kernel_launch(void* const* d_in, const int* in_sizes, int n_in,
                              void* d_out, int out_size) {
    const float* x      = (const float*)d_in[0];
    const float* enc_w  = (const float*)d_in[1];
    const float* enc_b  = (const float*)d_in[2];
    const float* log_dt = (const float*)d_in[3];
    const float* A_re   = (const float*)d_in[4];
    const float* A_im   = (const float*)d_in[5];
    const float* C_re   = (const float*)d_in[6];
    const float* C_im   = (const float*)d_in[7];
    const float* D      = (const float*)d_in[8];
    const float* out_w  = (const float*)d_in[9];
    const float* out_b  = (const float*)d_in[10];
    const float* ln_w   = (const float*)d_in[11];
    const float* ln_b   = (const float*)d_in[12];
    const float* dec_w  = (const float*)d_in[13];
    const float* dec_b  = (const float*)d_in[14];
    float* out = (float*)d_out;

    const int GEMM_SMEM = 2*A_STG + 2*B_STG;   // 71680
    cudaFuncSetAttribute(k_mma_glu, cudaFuncAttributeMaxDynamicSharedMemorySize, GEMM_SMEM);

    k_prep<<<(BB*LL*HH)/256, 256>>>(x, enc_w, enc_b, out_w,
                                    log_dt, A_re, A_im, C_re, C_im);

    for (int layer = 0; layer < NLAYERS; layer++) {
        dim3 lgrid(LL/32, BB);
        k_ln_t<<<lgrid, 256>>>(ln_w, ln_b, layer);
        k_scan<<<BB*HH, 256>>>(D, layer);
        dim3 ggrid(HH/64, (BB*LL)/128);
        k_mma_glu<<<ggrid, 512, GEMM_SMEM>>>(out_b, layer);
    }
    k_decoder<<<(BB*LL)/8, 256>>>(dec_w, dec_b, out);
}